// round 10
// baseline (speedup 1.0000x reference)
#include <cuda_runtime.h>
#include <math.h>
#include <stdint.h>

#define VSZ 32000
#define ESZ 512
#define HSZ 1024
#define SSZ 64
#define TSZ 64
#define BSZ 32
#define HB  (HSZ*BSZ)          // 32768
#define GXS (3*HSZ*BSZ)        // per-step gx stride
#define PAD_IDX 1
#define NEGV -100000.0f
#define NBLK 256               // persistent grid size

// ---------------- device scratch ----------------
__device__ float g_emb_src[SSZ*BSZ*ESZ];
__device__ float g_emb_dec[TSZ*BSZ*ESZ];
__device__ float g_gx_enc[SSZ*GXS];
__device__ float g_gx_dec[TSZ*GXS];
__device__ float g_enc_out_t[SSZ*BSZ*HSZ];      // [s][b][h]
__device__ float g_h0[2*HB];
__device__ float g_h1[2*HB];
__device__ float g_dh0[2*HB];
__device__ float g_dh1[2*HB];
__device__ float g_h1_all[TSZ*BSZ*HSZ];         // [m=(t,b)][h], tf32-rounded
__device__ float g_ctx_all[TSZ*BSZ*HSZ];        // [m][h], tf32-rounded
__device__ float g_cc_all[TSZ*BSZ*HSZ];         // [m][h], tf32-rounded
__device__ float g_wo_tf[VSZ*HSZ];
__device__ float g_wc_tf[HSZ*2*HSZ];
__device__ int           g_bar_cnt;
__device__ volatile int  g_bar_sense;

// ---------------- helpers ----------------
__device__ __forceinline__ uint32_t f2tf32(float f) {
    uint32_t u;
    asm("cvt.rna.tf32.f32 %0, %1;" : "=r"(u) : "f"(f));
    return u;
}
__device__ __forceinline__ void cp16(uint32_t s, const void* g) {
    asm volatile("cp.async.cg.shared.global [%0], [%1], 16;" :: "r"(s), "l"(g));
}
#define CP_COMMIT() asm volatile("cp.async.commit_group;" ::: "memory")
#define CP_WAIT(N)  asm volatile("cp.async.wait_group %0;" :: "n"(N) : "memory")

__device__ __forceinline__ void mma_tf32(float* c, const uint32_t* a, const uint32_t* b) {
    asm volatile(
        "mma.sync.aligned.m16n8k8.row.col.f32.tf32.tf32.f32 "
        "{%0,%1,%2,%3},{%4,%5,%6,%7},{%8,%9},{%0,%1,%2,%3};"
        : "+f"(c[0]), "+f"(c[1]), "+f"(c[2]), "+f"(c[3])
        : "r"(a[0]), "r"(a[1]), "r"(a[2]), "r"(a[3]), "r"(b[0]), "r"(b[1]));
}

// global barrier (sense-reversing); all NBLK blocks must be resident
__device__ __forceinline__ void gbar(int* sense) {
    __syncthreads();
    if (threadIdx.x == 0) {
        __threadfence();
        int s = (*sense ^= 1);
        if (atomicAdd(&g_bar_cnt, 1) == NBLK - 1) {
            atomicExch(&g_bar_cnt, 0);
            __threadfence();
            g_bar_sense = s;
        } else {
            while (g_bar_sense != s) __nanosleep(32);
        }
    }
    __syncthreads();
}

// ---------------- utility kernels ----------------
__global__ void zero_kernel(float* p, int n) {
    for (int i = blockIdx.x*blockDim.x + threadIdx.x; i < n; i += gridDim.x*blockDim.x)
        p[i] = 0.f;
}
__global__ void zero_h2_kernel(float* a, float* b) {
    int i = blockIdx.x*256 + threadIdx.x;
    if (i < HB) a[i] = 0.f; else b[i - HB] = 0.f;
}
__global__ void cvt_tf32_kernel(const float* __restrict__ in, float* __restrict__ out) {
    int i = blockIdx.x*256 + threadIdx.x;
    float4 v = ((const float4*)in)[i];
    uint4 u = make_uint4(f2tf32(v.x), f2tf32(v.y), f2tf32(v.z), f2tf32(v.w));
    ((uint4*)out)[i] = u;
}
__global__ void embed_kernel(const int* __restrict__ tok,
                             const float* __restrict__ emb,
                             float* __restrict__ out, int rows) {
    int idx = blockIdx.x*256 + threadIdx.x;
    if (idx >= rows*ESZ) return;
    int e = idx & (ESZ-1);
    int m = idx >> 9;
    out[idx] = emb[(size_t)tok[m]*ESZ + e];
}

// ---------------- input projection ----------------
__global__ __launch_bounds__(256) void proj_gemm(
    const float* __restrict__ X, const float* __restrict__ W,
    const float* __restrict__ bih, float* __restrict__ gx)
{
    __shared__ float Xs[2][16][64];
    __shared__ float Ws[2][16][64];
    int tid = threadIdx.x;
    int mb = blockIdx.x*64, nb = blockIdx.y*64;
    int lr = tid >> 2, lc = (tid & 3) * 4;
    const float* Xg = X + (size_t)(mb+lr)*ESZ + lc;
    const float* Wg = W + (size_t)(nb+lr)*ESZ + lc;
    int tm = (tid & 15) * 4, tn = (tid >> 4) * 4;

    float acc[16];
    #pragma unroll
    for (int i = 0; i < 16; i++) acc[i] = 0.f;

    float4 px = *(const float4*)Xg;
    float4 pw = *(const float4*)Wg;
    for (int c = 0; c < 32; c++) {
        int buf = c & 1;
        Xs[buf][lc+0][lr]=px.x; Xs[buf][lc+1][lr]=px.y; Xs[buf][lc+2][lr]=px.z; Xs[buf][lc+3][lr]=px.w;
        Ws[buf][lc+0][lr]=pw.x; Ws[buf][lc+1][lr]=pw.y; Ws[buf][lc+2][lr]=pw.z; Ws[buf][lc+3][lr]=pw.w;
        __syncthreads();
        if (c < 31) {
            px = *(const float4*)(Xg + (c+1)*16);
            pw = *(const float4*)(Wg + (c+1)*16);
        }
        #pragma unroll
        for (int kk = 0; kk < 16; kk++) {
            float4 av = *(const float4*)&Xs[buf][kk][tm];
            float4 wv = *(const float4*)&Ws[buf][kk][tn];
            acc[0]+=av.x*wv.x; acc[1]+=av.x*wv.y; acc[2]+=av.x*wv.z; acc[3]+=av.x*wv.w;
            acc[4]+=av.y*wv.x; acc[5]+=av.y*wv.y; acc[6]+=av.y*wv.z; acc[7]+=av.y*wv.w;
            acc[8]+=av.z*wv.x; acc[9]+=av.z*wv.y; acc[10]+=av.z*wv.z; acc[11]+=av.z*wv.w;
            acc[12]+=av.w*wv.x; acc[13]+=av.w*wv.y; acc[14]+=av.w*wv.z; acc[15]+=av.w*wv.w;
        }
        __syncthreads();
    }
    #pragma unroll
    for (int i = 0; i < 4; i++) {
        int m = mb + tm + i;
        int t = m >> 5, b = m & 31;
        #pragma unroll
        for (int j = 0; j < 4; j++) {
            int n = nb + tn + j;
            gx[(size_t)t*GXS + (size_t)n*BSZ + b] = acc[i*4+j] + bih[n];
        }
    }
}

// ---------------- persistent RNN: phase bodies ----------------
__device__ void l0_phase(float* Xd, const float* gx, const float* h_old,
                         const float* __restrict__ Whh, const float* __restrict__ bhh,
                         float* h_new, int tid, int lane, int p, int hf, int j)
{
    __shared__ float R0[4][3][32];
    const float* wr = Whh + (size_t)j*HSZ          + hf*512;
    const float* wz = Whh + (size_t)(HSZ+j)*HSZ    + hf*512;
    const float* wn = Whh + (size_t)(2*HSZ+j)*HSZ  + hf*512;
    float ar=0.f, az=0.f, an=0.f;

    for (int i = 0; i < 4; i++) {
        __syncthreads();
        #pragma unroll
        for (int it = 0; it < 8; it++) {
            int r = (tid >> 3) + it*32;
            int h = r >> 7, kk = r & 127;
            int gk = h*512 + i*128 + kk;
            float4 v = __ldcg((const float4*)(h_old + (size_t)gk*BSZ + (tid & 7)*4));
            *(float4*)&Xd[(h*128 + kk)*36 + (tid & 7)*4] = v;
        }
        __syncthreads();
        #pragma unroll
        for (int q = 0; q < 32; q++) {
            float4 r4 = *(const float4*)(wr + i*128 + q*4);
            float4 z4 = *(const float4*)(wz + i*128 + q*4);
            float4 n4 = *(const float4*)(wn + i*128 + q*4);
            float x0 = Xd[(hf*128 + q*4+0)*36 + lane], x1 = Xd[(hf*128 + q*4+1)*36 + lane];
            float x2 = Xd[(hf*128 + q*4+2)*36 + lane], x3 = Xd[(hf*128 + q*4+3)*36 + lane];
            ar += r4.x*x0 + r4.y*x1 + r4.z*x2 + r4.w*x3;
            az += z4.x*x0 + z4.y*x1 + z4.z*x2 + z4.w*x3;
            an += n4.x*x0 + n4.y*x1 + n4.z*x2 + n4.w*x3;
        }
    }
    if (hf == 1) { R0[p][0][lane]=ar; R0[p][1][lane]=az; R0[p][2][lane]=an; }
    __syncthreads();
    if (hf == 0) {
        float ghr = ar + R0[p][0][lane] + bhh[j];
        float ghz = az + R0[p][1][lane] + bhh[HSZ+j];
        float ghn = an + R0[p][2][lane] + bhh[2*HSZ+j];
        float gr = gx[(size_t)j*BSZ + lane]       + ghr;
        float gz = gx[(size_t)(HSZ+j)*BSZ + lane] + ghz;
        float r = 1.f/(1.f + expf(-gr));
        float z = 1.f/(1.f + expf(-gz));
        float n = tanhf(gx[(size_t)(2*HSZ+j)*BSZ + lane] + r*ghn);
        float hp = __ldcg(h_old + (size_t)j*BSZ + lane);
        h_new[(size_t)j*BSZ + lane] = (1.f - z)*n + z*hp;
    }
}

__device__ void l1_phase(float* Xd, const float* x0, const float* h1o,
                         const float* __restrict__ Wih, const float* __restrict__ bih,
                         const float* __restrict__ Whh, const float* __restrict__ bhh,
                         float* h_new, float* dest, bool roundDest,
                         int tid, int lane, int p, int hf, int j)
{
    #define XL(s,h,kk,b) Xd[(((s)*2+(h))*64+(kk))*36+(b)]
    __shared__ float R1[4][6][32];
    const float* wxr = Wih + (size_t)j*HSZ          + hf*512;
    const float* wxz = Wih + (size_t)(HSZ+j)*HSZ    + hf*512;
    const float* wxn = Wih + (size_t)(2*HSZ+j)*HSZ  + hf*512;
    const float* whr = Whh + (size_t)j*HSZ          + hf*512;
    const float* whz = Whh + (size_t)(HSZ+j)*HSZ    + hf*512;
    const float* whn = Whh + (size_t)(2*HSZ+j)*HSZ  + hf*512;
    float xr=0.f,xz=0.f,xn=0.f, hr=0.f,hz=0.f,hn=0.f;

    for (int i = 0; i < 8; i++) {
        __syncthreads();
        #pragma unroll
        for (int it = 0; it < 8; it++) {
            int r = (tid >> 3) + it*32;
            int src = r >> 7, rr = r & 127;
            int h = rr >> 6, kk = rr & 63;
            int gk = h*512 + i*64 + kk;
            const float* s = src ? h1o : x0;
            float4 v = __ldcg((const float4*)(s + (size_t)gk*BSZ + (tid & 7)*4));
            *(float4*)&XL(src, h, kk, (tid & 7)*4) = v;
        }
        __syncthreads();
        #pragma unroll
        for (int q = 0; q < 16; q++) {
            float4 a4 = *(const float4*)(wxr + i*64 + q*4);
            float4 b4 = *(const float4*)(wxz + i*64 + q*4);
            float4 c4 = *(const float4*)(wxn + i*64 + q*4);
            float4 d4 = *(const float4*)(whr + i*64 + q*4);
            float4 e4 = *(const float4*)(whz + i*64 + q*4);
            float4 f4 = *(const float4*)(whn + i*64 + q*4);
            float u0 = XL(0,hf,q*4+0,lane), u1 = XL(0,hf,q*4+1,lane);
            float u2 = XL(0,hf,q*4+2,lane), u3 = XL(0,hf,q*4+3,lane);
            float v0 = XL(1,hf,q*4+0,lane), v1 = XL(1,hf,q*4+1,lane);
            float v2 = XL(1,hf,q*4+2,lane), v3 = XL(1,hf,q*4+3,lane);
            xr += a4.x*u0 + a4.y*u1 + a4.z*u2 + a4.w*u3;
            xz += b4.x*u0 + b4.y*u1 + b4.z*u2 + b4.w*u3;
            xn += c4.x*u0 + c4.y*u1 + c4.z*u2 + c4.w*u3;
            hr += d4.x*v0 + d4.y*v1 + d4.z*v2 + d4.w*v3;
            hz += e4.x*v0 + e4.y*v1 + e4.z*v2 + e4.w*v3;
            hn += f4.x*v0 + f4.y*v1 + f4.z*v2 + f4.w*v3;
        }
    }
    if (hf == 1) {
        R1[p][0][lane]=xr; R1[p][1][lane]=xz; R1[p][2][lane]=xn;
        R1[p][3][lane]=hr; R1[p][4][lane]=hz; R1[p][5][lane]=hn;
    }
    __syncthreads();
    if (hf == 0) {
        float txr = xr + R1[p][0][lane] + bih[j];
        float txz = xz + R1[p][1][lane] + bih[HSZ+j];
        float txn = xn + R1[p][2][lane] + bih[2*HSZ+j];
        float thr = hr + R1[p][3][lane] + bhh[j];
        float thz = hz + R1[p][4][lane] + bhh[HSZ+j];
        float thn = hn + R1[p][5][lane] + bhh[2*HSZ+j];
        float r = 1.f/(1.f + expf(-(txr + thr)));
        float z = 1.f/(1.f + expf(-(txz + thz)));
        float n = tanhf(txn + r*thn);
        float hp = __ldcg(h1o + (size_t)j*BSZ + lane);
        float h = (1.f - z)*n + z*hp;
        h_new[(size_t)j*BSZ + lane] = h;
        float hd = roundDest ? __uint_as_float(f2tf32(h)) : h;
        dest[(size_t)lane*HSZ + j] = hd;
    }
    #undef XL
}

#define RNN_SMEM (2*2*64*36*4)  // 73728 B
__global__ __launch_bounds__(256, 2) void rnn_persistent(
    const float* gx_enc, const float* gx_dec,
    const float* eWhh0, const float* ebhh0,
    const float* eWih1, const float* ebih1,
    const float* eWhh1, const float* ebhh1,
    const float* dWhh0, const float* dbhh0,
    const float* dWih1, const float* dbih1,
    const float* dWhh1, const float* dbhh1,
    float* h0, float* h1, float* dh0, float* dh1,
    float* enc_out_t, float* h1_all)
{
    extern __shared__ float Xd[];
    int tid = threadIdx.x, w = tid >> 5, lane = tid & 31;
    int p = w & 3, hf = w >> 2;
    int j = blockIdx.x*4 + p;
    int sense = 0;

    // ---- encoder ----
    for (int t = 0; t < SSZ; t++) {
        int rp = t & 1, wp = rp ^ 1;
        l0_phase(Xd, gx_enc + (size_t)t*GXS, h0 + rp*HB, eWhh0, ebhh0,
                 h0 + wp*HB, tid, lane, p, hf, j);
        gbar(&sense);
        l1_phase(Xd, h0 + wp*HB, h1 + rp*HB, eWih1, ebih1, eWhh1, ebhh1,
                 h1 + wp*HB, enc_out_t + (size_t)t*BSZ*HSZ, false,
                 tid, lane, p, hf, j);
        gbar(&sense);
    }
    // final encoder hidden at parity 0 (S even)

    // ---- decoder ----
    for (int t = 0; t < TSZ-1; t++) {
        int wp = (t+1) & 1, rp = t & 1;
        const float* h0r = (t == 0) ? h0 : dh0 + rp*HB;
        const float* h1r = (t == 0) ? h1 : dh1 + rp*HB;
        l0_phase(Xd, gx_dec + (size_t)t*GXS, h0r, dWhh0, dbhh0,
                 dh0 + wp*HB, tid, lane, p, hf, j);
        gbar(&sense);
        l1_phase(Xd, dh0 + wp*HB, h1r, dWih1, dbih1, dWhh1, dbhh1,
                 dh1 + wp*HB, h1_all + (size_t)t*BSZ*HSZ, true,
                 tid, lane, p, hf, j);
        gbar(&sense);
    }
}

// ---------------- batched attention: grid (b=32, t=63) ----------------
__global__ __launch_bounds__(256) void attn_batched(
    const float* __restrict__ h1_all,     // [m=(t,b)][H]
    const float* __restrict__ enc_out_t,  // [S][B][H]
    const int*   __restrict__ src_tokens, // [S][B]
    float* __restrict__ ctx_all)          // [m][H], tf32-rounded
{
    int b = blockIdx.x, t = blockIdx.y;
    const float* h1t = h1_all + (size_t)t*BSZ*HSZ;
    float* ctx = ctx_all + (size_t)t*BSZ*HSZ;
    int w = threadIdx.x >> 5, lane = threadIdx.x & 31;
    __shared__ float sc[64];

    float4 q[8];
    #pragma unroll
    for (int c = 0; c < 8; c++)
        q[c] = *(const float4*)(h1t + (size_t)b*HSZ + c*128 + lane*4);

    #pragma unroll
    for (int i = 0; i < 8; i++) {
        int s = w*8 + i;
        const float* e = enc_out_t + ((size_t)s*BSZ + b)*HSZ;
        float acc = 0.f;
        #pragma unroll
        for (int c = 0; c < 8; c++) {
            float4 ev = *(const float4*)(e + c*128 + lane*4);
            acc += q[c].x*ev.x + q[c].y*ev.y + q[c].z*ev.z + q[c].w*ev.w;
        }
        #pragma unroll
        for (int off = 16; off; off >>= 1)
            acc += __shfl_xor_sync(0xffffffffu, acc, off);
        if (lane == 0)
            sc[s] = (src_tokens[s*BSZ + b] != PAD_IDX) ? acc : NEGV;
    }
    __syncthreads();

    if (w == 0) {
        float v0 = sc[lane], v1 = sc[lane+32];
        float m = fmaxf(v0, v1);
        #pragma unroll
        for (int off = 16; off; off >>= 1)
            m = fmaxf(m, __shfl_xor_sync(0xffffffffu, m, off));
        float e0 = expf(v0 - m), e1 = expf(v1 - m);
        float ssum = e0 + e1;
        #pragma unroll
        for (int off = 16; off; off >>= 1)
            ssum += __shfl_xor_sync(0xffffffffu, ssum, off);
        sc[lane]    = e0/ssum;
        sc[lane+32] = e1/ssum;
    }
    __syncthreads();

    float4 a4 = make_float4(0.f, 0.f, 0.f, 0.f);
    for (int s = 0; s < SSZ; s++) {
        float at = sc[s];
        float4 ev = *(const float4*)(enc_out_t + ((size_t)s*BSZ + b)*HSZ + threadIdx.x*4);
        a4.x += at*ev.x; a4.y += at*ev.y; a4.z += at*ev.z; a4.w += at*ev.w;
    }
    uint4 u = make_uint4(f2tf32(a4.x), f2tf32(a4.y), f2tf32(a4.z), f2tf32(a4.w));
    *(uint4*)(ctx + (size_t)b*HSZ + threadIdx.x*4) = u;
}

// ---------------- batched cc GEMM via mma (M=2048, N=1024, K=2048) ----
// cc[m][n] = tf32(tanh([h1_all|ctx_all][m]·Wc[n] + bc[n])); tile 128m x 128n.
#define CC_SMEM ((2*128*36 + 2*128*36)*4)
__global__ __launch_bounds__(256) void cc_mma(
    const float* __restrict__ h1a,   // [2048][1024] tf32 bits
    const float* __restrict__ ctxa,  // [2048][1024] tf32 bits
    const float* __restrict__ wc,    // [1024][2048] tf32 bits
    const float* __restrict__ bc,
    float* __restrict__ cc)          // [2048][1024]
{
    extern __shared__ uint32_t sm[];
    uint32_t* As = sm;                    // [2][128][36]
    uint32_t* Bs = sm + 2*128*36;         // [2][128][36]

    int tid = threadIdx.x, w = tid >> 5, lane = tid & 31;
    int g = lane >> 2, t4 = lane & 3;
    int warpM = w & 1, warpN = w >> 1;    // 2 x 4 warps
    int mb = blockIdx.x * 128, nb = blockIdx.y * 128;

    uint32_t as_s = (uint32_t)__cvta_generic_to_shared(As);
    uint32_t bs_s = (uint32_t)__cvta_generic_to_shared(Bs);

    float acc[4][4][4];
    #pragma unroll
    for (int i = 0; i < 4; i++)
        #pragma unroll
        for (int jj = 0; jj < 4; jj++)
            #pragma unroll
            for (int k = 0; k < 4; k++) acc[i][jj][k] = 0.f;

    auto issue = [&](int ch) {
        int kc0 = ch*32, buf = ch & 1;
        uint32_t ao = as_s + buf*128*36*4;
        uint32_t bo2 = bs_s + buf*128*36*4;
        // A tile: 128 rows x 32 floats = 1024 float4  -> 4 iterations
        #pragma unroll
        for (int i = 0; i < 4; i++) {
            int idx = tid + i*256, r = idx >> 3, c = (idx & 7)*4;
            int k = kc0 + c;
            const float* src = (k < HSZ) ? (h1a + (size_t)(mb+r)*HSZ + k)
                                         : (ctxa + (size_t)(mb+r)*HSZ + (k - HSZ));
            cp16(ao + (r*36 + c)*4, src);
        }
        // B tile: 128 rows x 32 floats = 1024 float4  -> 4 iterations
        #pragma unroll
        for (int i = 0; i < 4; i++) {
            int idx = tid + i*256, r = idx >> 3, c = (idx & 7)*4;
            cp16(bo2 + (r*36 + c)*4, wc + (size_t)(nb+r)*(2*HSZ) + kc0 + c);
        }
        CP_COMMIT();
    };

    issue(0);
    for (int ch = 0; ch < 64; ch++) {
        if (ch < 63) { issue(ch+1); CP_WAIT(1); } else { CP_WAIT(0); }
        __syncthreads();
        int buf = ch & 1;
        const uint32_t* A0 = As + buf*128*36 + (warpM*64 + g)*36;
        const uint32_t* B0 = Bs + buf*128*36 + (warpN*32 + g)*36;
        #pragma unroll
        for (int ks = 0; ks < 4; ks++) {
            uint32_t a[4][4], b[4][2];
            #pragma unroll
            for (int mf = 0; mf < 4; mf++) {
                const uint32_t* ap = A0 + mf*16*36 + ks*8 + t4;
                a[mf][0] = ap[0]; a[mf][1] = ap[8*36]; a[mf][2] = ap[4]; a[mf][3] = ap[8*36+4];
            }
            #pragma unroll
            for (int nf = 0; nf < 4; nf++) {
                const uint32_t* bp = B0 + nf*8*36 + ks*8 + t4;
                b[nf][0] = bp[0]; b[nf][1] = bp[4];
            }
            #pragma unroll
            for (int mf = 0; mf < 4; mf++)
                #pragma unroll
                for (int nf = 0; nf < 4; nf++)
                    mma_tf32(acc[mf][nf], a[mf], b[nf]);
        }
        __syncthreads();
    }

    #pragma unroll
    for (int nf = 0; nf < 4; nf++) {
        int n = nb + warpN*32 + nf*8 + t4*2;
        float b0v = bc[n], b1v = bc[n+1];
        #pragma unroll
        for (int mf = 0; mf < 4; mf++) {
            int m_lo = mb + warpM*64 + mf*16 + g;
            int m_hi = m_lo + 8;
            if (m_lo < (TSZ-1)*BSZ) {
                cc[(size_t)m_lo*HSZ + n  ] = __uint_as_float(f2tf32(tanhf(acc[mf][nf][0] + b0v)));
                cc[(size_t)m_lo*HSZ + n+1] = __uint_as_float(f2tf32(tanhf(acc[mf][nf][1] + b1v)));
            }
            if (m_hi < (TSZ-1)*BSZ) {
                cc[(size_t)m_hi*HSZ + n  ] = __uint_as_float(f2tf32(tanhf(acc[mf][nf][2] + b0v)));
                cc[(size_t)m_hi*HSZ + n+1] = __uint_as_float(f2tf32(tanhf(acc[mf][nf][3] + b1v)));
            }
        }
    }
}

// ---------------- logits GEMM via mma.sync tf32 ----------------
#define LG_SMEM ((2*128*36 + 2*256*36)*4)
__global__ __launch_bounds__(256) void logits_mma(
    const float* __restrict__ cc, const float* __restrict__ wo,
    const float* __restrict__ bo, float* __restrict__ out)
{
    extern __shared__ uint32_t sm[];
    uint32_t* As = sm;
    uint32_t* Bs = sm + 2*128*36;

    int tid = threadIdx.x, w = tid >> 5, lane = tid & 31;
    int g = lane >> 2, t4 = lane & 3;
    int warpM = w & 1, warpN = w >> 1;
    int mb = blockIdx.x * 128, vb = blockIdx.y * 256;

    const float* Ag = cc + (size_t)mb*HSZ;
    const float* Bg = wo + (size_t)vb*HSZ;
    uint32_t as_s = (uint32_t)__cvta_generic_to_shared(As);
    uint32_t bs_s = (uint32_t)__cvta_generic_to_shared(Bs);

    float acc[4][8][4];
    #pragma unroll
    for (int i = 0; i < 4; i++)
        #pragma unroll
        for (int jj = 0; jj < 8; jj++)
            #pragma unroll
            for (int k = 0; k < 4; k++) acc[i][jj][k] = 0.f;

    {
        #pragma unroll
        for (int i = 0; i < 4; i++) {
            int idx = tid + i*256, r = idx >> 3, c = (idx & 7)*4;
            cp16(as_s + (r*36 + c)*4, Ag + (size_t)r*HSZ + c);
        }
        #pragma unroll
        for (int i = 0; i < 8; i++) {
            int idx = tid + i*256, r = idx >> 3, c = (idx & 7)*4;
            cp16(bs_s + (r*36 + c)*4, Bg + (size_t)r*HSZ + c);
        }
        CP_COMMIT();
    }

    for (int ch = 0; ch < 32; ch++) {
        if (ch < 31) {
            int kc0 = (ch+1)*32, buf = (ch+1) & 1;
            uint32_t ao = as_s + buf*128*36*4;
            uint32_t bo_s = bs_s + buf*256*36*4;
            #pragma unroll
            for (int i = 0; i < 4; i++) {
                int idx = tid + i*256, r = idx >> 3, c = (idx & 7)*4;
                cp16(ao + (r*36 + c)*4, Ag + (size_t)r*HSZ + kc0 + c);
            }
            #pragma unroll
            for (int i = 0; i < 8; i++) {
                int idx = tid + i*256, r = idx >> 3, c = (idx & 7)*4;
                cp16(bo_s + (r*36 + c)*4, Bg + (size_t)r*HSZ + kc0 + c);
            }
            CP_COMMIT();
            CP_WAIT(1);
        } else {
            CP_WAIT(0);
        }
        __syncthreads();

        int buf = ch & 1;
        const uint32_t* A0 = As + buf*128*36 + (warpM*64 + g)*36;
        const uint32_t* B0 = Bs + buf*256*36 + (warpN*64 + g)*36;

        #pragma unroll
        for (int ks = 0; ks < 4; ks++) {
            uint32_t a[4][4], b[8][2];
            #pragma unroll
            for (int mf = 0; mf < 4; mf++) {
                const uint32_t* ap = A0 + mf*16*36 + ks*8 + t4;
                a[mf][0] = ap[0]; a[mf][1] = ap[8*36]; a[mf][2] = ap[4]; a[mf][3] = ap[8*36+4];
            }
            #pragma unroll
            for (int nf = 0; nf < 8; nf++) {
                const uint32_t* bp = B0 + nf*8*36 + ks*8 + t4;
                b[nf][0] = bp[0]; b[nf][1] = bp[4];
            }
            #pragma unroll
            for (int mf = 0; mf < 4; mf++)
                #pragma unroll
                for (int nf = 0; nf < 8; nf++)
                    mma_tf32(acc[mf][nf], a[mf], b[nf]);
        }
        __syncthreads();
    }

    #pragma unroll
    for (int nf = 0; nf < 8; nf++) {
        int v = vb + warpN*64 + nf*8 + t4*2;
        float b0v = bo[v], b1v = bo[v+1];
        #pragma unroll
        for (int mf = 0; mf < 4; mf++) {
            int m_lo = mb + warpM*64 + mf*16 + g;
            int m_hi = m_lo + 8;
            if (m_lo < (TSZ-1)*BSZ) {
                out[(size_t)(m_lo + BSZ)*VSZ + v    ] = acc[mf][nf][0] + b0v;
                out[(size_t)(m_lo + BSZ)*VSZ + v + 1] = acc[mf][nf][1] + b1v;
            }
            if (m_hi < (TSZ-1)*BSZ) {
                out[(size_t)(m_hi + BSZ)*VSZ + v    ] = acc[mf][nf][2] + b0v;
                out[(size_t)(m_hi + BSZ)*VSZ + v + 1] = acc[mf][nf][3] + b1v;
            }
        }
    }
}

// ---------------- host ----------------
extern "C" void kernel_launch(void* const* d_in, const int* in_sizes, int n_in,
                              void* d_out, int out_size) {
    const int*   src_tokens = (const int*)  d_in[0];
    const int*   tgt_tokens = (const int*)  d_in[1];
    const float* enc_emb    = (const float*)d_in[2];
    const float* enc_Wih0   = (const float*)d_in[3];
    const float* enc_Whh0   = (const float*)d_in[4];
    const float* enc_bih0   = (const float*)d_in[5];
    const float* enc_bhh0   = (const float*)d_in[6];
    const float* enc_Wih1   = (const float*)d_in[7];
    const float* enc_Whh1   = (const float*)d_in[8];
    const float* enc_bih1   = (const float*)d_in[9];
    const float* enc_bhh1   = (const float*)d_in[10];
    const float* dec_emb    = (const float*)d_in[11];
    const float* dec_Wih0   = (const float*)d_in[12];
    const float* dec_Whh0   = (const float*)d_in[13];
    const float* dec_bih0   = (const float*)d_in[14];
    const float* dec_bhh0   = (const float*)d_in[15];
    const float* dec_Wih1   = (const float*)d_in[16];
    const float* dec_Whh1   = (const float*)d_in[17];
    const float* dec_bih1   = (const float*)d_in[18];
    const float* dec_bhh1   = (const float*)d_in[19];
    const float* Wc         = (const float*)d_in[20];
    const float* bc         = (const float*)d_in[21];
    const float* Wo         = (const float*)d_in[22];
    const float* bo         = (const float*)d_in[23];
    float* out = (float*)d_out;

    float *emb_src, *emb_dec, *gx_enc, *gx_dec, *enc_out_t;
    float *h0, *h1, *dh0, *dh1, *h1_all, *ctx_all, *cc_all, *wo_tf, *wc_tf;
    cudaGetSymbolAddress((void**)&emb_src,   g_emb_src);
    cudaGetSymbolAddress((void**)&emb_dec,   g_emb_dec);
    cudaGetSymbolAddress((void**)&gx_enc,    g_gx_enc);
    cudaGetSymbolAddress((void**)&gx_dec,    g_gx_dec);
    cudaGetSymbolAddress((void**)&enc_out_t, g_enc_out_t);
    cudaGetSymbolAddress((void**)&h0,        g_h0);
    cudaGetSymbolAddress((void**)&h1,        g_h1);
    cudaGetSymbolAddress((void**)&dh0,       g_dh0);
    cudaGetSymbolAddress((void**)&dh1,       g_dh1);
    cudaGetSymbolAddress((void**)&h1_all,    g_h1_all);
    cudaGetSymbolAddress((void**)&ctx_all,   g_ctx_all);
    cudaGetSymbolAddress((void**)&cc_all,    g_cc_all);
    cudaGetSymbolAddress((void**)&wo_tf,     g_wo_tf);
    cudaGetSymbolAddress((void**)&wc_tf,     g_wc_tf);

    cudaFuncSetAttribute(rnn_persistent, cudaFuncAttributeMaxDynamicSharedMemorySize, RNN_SMEM);
    cudaFuncSetAttribute(cc_mma,        cudaFuncAttributeMaxDynamicSharedMemorySize, CC_SMEM);
    cudaFuncSetAttribute(logits_mma,    cudaFuncAttributeMaxDynamicSharedMemorySize, LG_SMEM);

    // prep (single stream; graph is a simple chain)
    zero_kernel<<<1024, 256>>>(out, BSZ*VSZ);
    zero_h2_kernel<<<(2*HB)/256, 256>>>(h0, h1);
    embed_kernel<<<(SSZ*BSZ*ESZ)/256, 256>>>(src_tokens, enc_emb, emb_src, SSZ*BSZ);
    embed_kernel<<<((TSZ-1)*BSZ*ESZ)/256, 256>>>(tgt_tokens, dec_emb, emb_dec, (TSZ-1)*BSZ);
    proj_gemm<<<dim3(32, 48), 256>>>(emb_src, enc_Wih0, enc_bih0, gx_enc);
    proj_gemm<<<dim3(32, 48), 256>>>(emb_dec, dec_Wih0, dec_bih0, gx_dec);
    cvt_tf32_kernel<<<(VSZ*HSZ/4)/256, 256>>>(Wo, wo_tf);
    cvt_tf32_kernel<<<(HSZ*2*HSZ/4)/256, 256>>>(Wc, wc_tf);

    // whole recurrence: ONE launch
    rnn_persistent<<<NBLK, 256, RNN_SMEM>>>(
        gx_enc, gx_dec,
        enc_Whh0, enc_bhh0, enc_Wih1, enc_bih1, enc_Whh1, enc_bhh1,
        dec_Whh0, dec_bhh0, dec_Wih1, dec_bih1, dec_Whh1, dec_bhh1,
        h0, h1, dh0, dh1, enc_out_t, h1_all);

    // batched epilogue
    attn_batched<<<dim3(BSZ, TSZ-1), 256>>>(h1_all, enc_out_t, src_tokens, ctx_all);
    cc_mma<<<dim3(16, 8), 256, CC_SMEM>>>(h1_all, ctx_all, wc_tf, bc, cc_all);
    logits_mma<<<dim3(16, 125), 256, LG_SMEM>>>(cc_all, wo_tf, bo, out);
}

// round 13
// speedup vs baseline: 1.3652x; 1.3652x over previous
#include <cuda_runtime.h>
#include <math.h>
#include <stdint.h>

#define VSZ 32000
#define ESZ 512
#define HSZ 1024
#define SSZ 64
#define TSZ 64
#define BSZ 32
#define BH  (BSZ*HSZ)          // 32768
#define GXS (3*HSZ*BSZ)
#define WSZ (3*HSZ*HSZ)        // 3.1M floats per recurrent weight matrix
#define PAD_IDX 1
#define NEGV -100000.0f
#define NBLK 128               // persistent grid (<= 1 wave, all resident)

// smem layout for recurrent phases (floats)
#define TW 36
#define OFF_AHI 0
#define OFF_ALO (64*TW)
#define OFF_XHI (128*TW)
#define OFF_XLO (192*TW)
#define BUFF (256*TW)
#define RNN_SMEM (2*BUFF*4)    // 73728 B

// ---------------- device scratch ----------------
__device__ float g_emb_src[SSZ*BSZ*ESZ];
__device__ float g_emb_dec[TSZ*BSZ*ESZ];
__device__ float g_gx_enc[SSZ*GXS];             // [s][n][b] (+bih0)
__device__ float g_gx_dec[TSZ*GXS];
__device__ float g_enc_out_t[SSZ*BH];           // [s][b][h]
// hidden states, [parity][b][h] as fp32 + tf32 hi/lo split
__device__ float g_h0_32[2*BH], g_h0_hi[2*BH], g_h0_lo[2*BH];
__device__ float g_h1_32[2*BH], g_h1_hi[2*BH], g_h1_lo[2*BH];
__device__ float g_dh0_32[2*BH], g_dh0_hi[2*BH], g_dh0_lo[2*BH];
__device__ float g_dh1_32[2*BH], g_dh1_hi[2*BH], g_dh1_lo[2*BH];
__device__ float g_h1_all[TSZ*BH];              // [t][b][h] tf32-rounded
__device__ float g_ctx_all[TSZ*BH];
__device__ float g_cc_all[TSZ*BH];
__device__ float g_wo_tf[VSZ*HSZ];
__device__ float g_wc_tf[HSZ*2*HSZ];
// recurrent weights split: order eWhh0,eWih1,eWhh1,dWhh0,dWih1,dWhh1
__device__ float g_whi[6*WSZ];
__device__ float g_wlo[6*WSZ];
__device__ int           g_bar_cnt;
__device__ volatile int  g_bar_sense;

// ---------------- helpers ----------------
__device__ __forceinline__ uint32_t f2tf32(float f) {
    uint32_t u;
    asm("cvt.rna.tf32.f32 %0, %1;" : "=r"(u) : "f"(f));
    return u;
}
__device__ __forceinline__ float tf32v(float f) { return __uint_as_float(f2tf32(f)); }
__device__ __forceinline__ void cp16(uint32_t s, const void* g) {
    asm volatile("cp.async.cg.shared.global [%0], [%1], 16;" :: "r"(s), "l"(g));
}
#define CP_COMMIT() asm volatile("cp.async.commit_group;" ::: "memory")
#define CP_WAIT(N)  asm volatile("cp.async.wait_group %0;" :: "n"(N) : "memory")

__device__ __forceinline__ void mma_tf32(float* c, const uint32_t* a, const uint32_t* b) {
    asm volatile(
        "mma.sync.aligned.m16n8k8.row.col.f32.tf32.tf32.f32 "
        "{%0,%1,%2,%3},{%4,%5,%6,%7},{%8,%9},{%0,%1,%2,%3};"
        : "+f"(c[0]), "+f"(c[1]), "+f"(c[2]), "+f"(c[3])
        : "r"(a[0]), "r"(a[1]), "r"(a[2]), "r"(a[3]), "r"(b[0]), "r"(b[1]));
}

// Global barrier (sense-reversing). CRITICAL: local sense seeded from the
// persistent global so ANY barrier-count parity from a previous launch (or
// graph replay) is handled — no writer touches g_bar_sense until all NBLK
// blocks have arrived at the first barrier, so the entry read is race-free.
__device__ __forceinline__ void gbar(int* sense) {
    __syncthreads();
    if (threadIdx.x == 0) {
        __threadfence();
        int s = (*sense ^= 1);
        if (atomicAdd(&g_bar_cnt, 1) == NBLK - 1) {
            atomicExch(&g_bar_cnt, 0);
            __threadfence();
            g_bar_sense = s;
        } else {
            while (g_bar_sense != s) __nanosleep(32);
        }
    }
    __syncthreads();
}

// ---------------- utility kernels ----------------
__global__ void zero_kernel(float* p, int n) {
    for (int i = blockIdx.x*blockDim.x + threadIdx.x; i < n; i += gridDim.x*blockDim.x)
        p[i] = 0.f;
}
__global__ void cvt_tf32_kernel(const float* __restrict__ in, float* __restrict__ out) {
    int i = blockIdx.x*256 + threadIdx.x;
    float4 v = ((const float4*)in)[i];
    uint4 u = make_uint4(f2tf32(v.x), f2tf32(v.y), f2tf32(v.z), f2tf32(v.w));
    ((uint4*)out)[i] = u;
}
__global__ void embed_kernel(const int* __restrict__ tok,
                             const float* __restrict__ emb,
                             float* __restrict__ out, int rows) {
    int idx = blockIdx.x*256 + threadIdx.x;
    if (idx >= rows*ESZ) return;
    int e = idx & (ESZ-1);
    int m = idx >> 9;
    out[idx] = emb[(size_t)tok[m]*ESZ + e];
}
// split 6 recurrent weight matrices into tf32 hi/lo
__global__ void split_all(const float* w0, const float* w1, const float* w2,
                          const float* w3, const float* w4, const float* w5) {
    const int N4 = WSZ/4;
    int idx = blockIdx.x*256 + threadIdx.x;
    int m = idx / N4, i = idx - m*N4;
    const float* w = m==0?w0: m==1?w1: m==2?w2: m==3?w3: m==4?w4: w5;
    float4 v = ((const float4*)w)[i];
    float4 hi, lo;
    hi.x = tf32v(v.x); lo.x = tf32v(v.x - hi.x);
    hi.y = tf32v(v.y); lo.y = tf32v(v.y - hi.y);
    hi.z = tf32v(v.z); lo.z = tf32v(v.z - hi.z);
    hi.w = tf32v(v.w); lo.w = tf32v(v.w - hi.w);
    ((float4*)(g_whi + (size_t)m*WSZ))[i] = hi;
    ((float4*)(g_wlo + (size_t)m*WSZ))[i] = lo;
}

// ---------------- input projection ----------------
__global__ __launch_bounds__(256) void proj_gemm(
    const float* __restrict__ X, const float* __restrict__ W,
    const float* __restrict__ bih, float* __restrict__ gx)
{
    __shared__ float Xs[2][16][64];
    __shared__ float Ws[2][16][64];
    int tid = threadIdx.x;
    int mb = blockIdx.x*64, nb = blockIdx.y*64;
    int lr = tid >> 2, lc = (tid & 3) * 4;
    const float* Xg = X + (size_t)(mb+lr)*ESZ + lc;
    const float* Wg = W + (size_t)(nb+lr)*ESZ + lc;
    int tm = (tid & 15) * 4, tn = (tid >> 4) * 4;

    float acc[16];
    #pragma unroll
    for (int i = 0; i < 16; i++) acc[i] = 0.f;

    float4 px = *(const float4*)Xg;
    float4 pw = *(const float4*)Wg;
    for (int c = 0; c < 32; c++) {
        int buf = c & 1;
        Xs[buf][lc+0][lr]=px.x; Xs[buf][lc+1][lr]=px.y; Xs[buf][lc+2][lr]=px.z; Xs[buf][lc+3][lr]=px.w;
        Ws[buf][lc+0][lr]=pw.x; Ws[buf][lc+1][lr]=pw.y; Ws[buf][lc+2][lr]=pw.z; Ws[buf][lc+3][lr]=pw.w;
        __syncthreads();
        if (c < 31) {
            px = *(const float4*)(Xg + (c+1)*16);
            pw = *(const float4*)(Wg + (c+1)*16);
        }
        #pragma unroll
        for (int kk = 0; kk < 16; kk++) {
            float4 av = *(const float4*)&Xs[buf][kk][tm];
            float4 wv = *(const float4*)&Ws[buf][kk][tn];
            acc[0]+=av.x*wv.x; acc[1]+=av.x*wv.y; acc[2]+=av.x*wv.z; acc[3]+=av.x*wv.w;
            acc[4]+=av.y*wv.x; acc[5]+=av.y*wv.y; acc[6]+=av.y*wv.z; acc[7]+=av.y*wv.w;
            acc[8]+=av.z*wv.x; acc[9]+=av.z*wv.y; acc[10]+=av.z*wv.z; acc[11]+=av.z*wv.w;
            acc[12]+=av.w*wv.x; acc[13]+=av.w*wv.y; acc[14]+=av.w*wv.z; acc[15]+=av.w*wv.w;
        }
        __syncthreads();
    }
    #pragma unroll
    for (int i = 0; i < 4; i++) {
        int m = mb + tm + i;
        int t = m >> 5, b = m & 31;
        #pragma unroll
        for (int j = 0; j < 4; j++) {
            int n = nb + tn + j;
            gx[(size_t)t*GXS + (size_t)n*BSZ + b] = acc[i*4+j] + bih[n];
        }
    }
}

// ---------------- persistent recurrent phases (3xtf32 mma) ----------------
__device__ __forceinline__ void mma_phase_l0(
    float* S, uint32_t s_base,
    const float* Ahi, const float* Alo,
    const float* Xhi, const float* Xlo, const float* hold32,
    const float* gx, const float* __restrict__ bhh,
    float* w32, float* whi, float* wlo,
    int tid, int j0)
{
    int w = tid>>5, lane = tid&31;
    int mt = (w>>2)&1, nt = w&3, g = lane>>2, t4 = lane&3;
    float acc[4] = {0.f,0.f,0.f,0.f};

    auto issue = [&](int ch) {
        int kc0 = ch*32, buf = ch&1;
        uint32_t base = s_base + buf*BUFF*4;
        int r = tid>>3, c = (tid&7)*4;
        int gate = r>>3, jj2 = r&7;
        size_t grow = (size_t)((gate<3 ? gate*HSZ : 0) + j0 + jj2);
        cp16(base + (OFF_AHI + r*TW + c)*4, Ahi + grow*HSZ + kc0 + c);
        cp16(base + (OFF_ALO + r*TW + c)*4, Alo + grow*HSZ + kc0 + c);
        cp16(base + (OFF_XHI + r*TW + c)*4, Xhi + (size_t)r*HSZ + kc0 + c);
        cp16(base + (OFF_XLO + r*TW + c)*4, Xlo + (size_t)r*HSZ + kc0 + c);
        CP_COMMIT();
    };

    issue(0);
    for (int ch = 0; ch < 32; ch++) {
        if (ch < 31) { issue(ch+1); CP_WAIT(1); } else { CP_WAIT(0); }
        __syncthreads();
        const uint32_t* B = (const uint32_t*)S + (ch&1)*BUFF;
        int arow = mt*16 + g, xrow = nt*8 + g;
        #pragma unroll
        for (int ks = 0; ks < 4; ks++) {
            const uint32_t* ah = B + OFF_AHI + arow*TW + ks*8 + t4;
            const uint32_t* al = B + OFF_ALO + arow*TW + ks*8 + t4;
            const uint32_t* bh = B + OFF_XHI + xrow*TW + ks*8 + t4;
            const uint32_t* bl = B + OFF_XLO + xrow*TW + ks*8 + t4;
            uint32_t a0[4] = {ah[0], ah[8*TW], ah[4], ah[8*TW+4]};
            uint32_t a1[4] = {al[0], al[8*TW], al[4], al[8*TW+4]};
            uint32_t b0[2] = {bh[0], bh[4]};
            uint32_t b1[2] = {bl[0], bl[4]};
            mma_tf32(acc, a0, b0);
            mma_tf32(acc, a0, b1);
            mma_tf32(acc, a1, b0);
        }
        __syncthreads();
    }
    // exchange C through smem and combine
    float* Cs = S;   // [32][33], rows 0..23 valid
    int r0 = mt*16 + g, c0 = nt*8 + t4*2;
    Cs[r0*33 + c0] = acc[0]; Cs[r0*33 + c0 + 1] = acc[1];
    if (mt == 0) { Cs[(r0+8)*33 + c0] = acc[2]; Cs[(r0+8)*33 + c0 + 1] = acc[3]; }
    __syncthreads();

    int jj = tid>>5, b = tid&31, j = j0 + jj;
    float ghr = Cs[jj*33 + b]      + bhh[j];
    float ghz = Cs[(8+jj)*33 + b]  + bhh[HSZ+j];
    float ghn = Cs[(16+jj)*33 + b] + bhh[2*HSZ+j];
    float gr = gx[(size_t)j*BSZ + b]         + ghr;
    float gz = gx[(size_t)(HSZ+j)*BSZ + b]   + ghz;
    float rr = 1.f/(1.f + expf(-gr));
    float zz = 1.f/(1.f + expf(-gz));
    float nn = tanhf(gx[(size_t)(2*HSZ+j)*BSZ + b] + rr*ghn);
    float hp = __ldcg(hold32 + (size_t)b*HSZ + j);
    float h = (1.f - zz)*nn + zz*hp;
    size_t o = (size_t)b*HSZ + j;
    w32[o] = h;
    float hi = tf32v(h);
    whi[o] = hi;
    wlo[o] = tf32v(h - hi);
}

__device__ __forceinline__ void mma_phase_l1(
    float* S, uint32_t s_base,
    const float* A0hi, const float* A0lo,    // Wih1
    const float* A1hi, const float* A1lo,    // Whh1
    const float* X0hi, const float* X0lo,    // x0 [b][h]
    const float* X1hi, const float* X1lo,    // h1o [b][h]
    const float* h1o32,
    const float* __restrict__ bih, const float* __restrict__ bhh,
    float* w32, float* whi, float* wlo,
    float* dest, bool destHi,
    int tid, int j0)
{
    int w = tid>>5, lane = tid&31;
    int mt = (w>>2)&1, nt = w&3, g = lane>>2, t4 = lane&3;
    float acc[2][4] = {{0.f,0.f,0.f,0.f},{0.f,0.f,0.f,0.f}};

    auto issue = [&](int ch) {
        int kc0 = ch*32, buf = ch&1;
        uint32_t base = s_base + buf*BUFF*4;
        int r = tid>>3, c = (tid&7)*4;
        int gate = r>>3, jj2 = r&7;
        size_t grow = (size_t)((gate<3 ? gate*HSZ : 0) + j0 + jj2);
        cp16(base + (OFF_AHI + r*TW + c)*4,        A0hi + grow*HSZ + kc0 + c);
        cp16(base + (OFF_AHI + (32+r)*TW + c)*4,   A1hi + grow*HSZ + kc0 + c);
        cp16(base + (OFF_ALO + r*TW + c)*4,        A0lo + grow*HSZ + kc0 + c);
        cp16(base + (OFF_ALO + (32+r)*TW + c)*4,   A1lo + grow*HSZ + kc0 + c);
        cp16(base + (OFF_XHI + r*TW + c)*4,        X0hi + (size_t)r*HSZ + kc0 + c);
        cp16(base + (OFF_XHI + (32+r)*TW + c)*4,   X1hi + (size_t)r*HSZ + kc0 + c);
        cp16(base + (OFF_XLO + r*TW + c)*4,        X0lo + (size_t)r*HSZ + kc0 + c);
        cp16(base + (OFF_XLO + (32+r)*TW + c)*4,   X1lo + (size_t)r*HSZ + kc0 + c);
        CP_COMMIT();
    };

    issue(0);
    for (int ch = 0; ch < 32; ch++) {
        if (ch < 31) { issue(ch+1); CP_WAIT(1); } else { CP_WAIT(0); }
        __syncthreads();
        const uint32_t* B = (const uint32_t*)S + (ch&1)*BUFF;
        #pragma unroll
        for (int g2 = 0; g2 < 2; g2++) {
            int arow = g2*32 + mt*16 + g, xrow = g2*32 + nt*8 + g;
            #pragma unroll
            for (int ks = 0; ks < 4; ks++) {
                const uint32_t* ah = B + OFF_AHI + arow*TW + ks*8 + t4;
                const uint32_t* al = B + OFF_ALO + arow*TW + ks*8 + t4;
                const uint32_t* bh = B + OFF_XHI + xrow*TW + ks*8 + t4;
                const uint32_t* bl = B + OFF_XLO + xrow*TW + ks*8 + t4;
                uint32_t a0[4] = {ah[0], ah[8*TW], ah[4], ah[8*TW+4]};
                uint32_t a1[4] = {al[0], al[8*TW], al[4], al[8*TW+4]};
                uint32_t b0[2] = {bh[0], bh[4]};
                uint32_t b1[2] = {bl[0], bl[4]};
                mma_tf32(acc[g2], a0, b0);
                mma_tf32(acc[g2], a0, b1);
                mma_tf32(acc[g2], a1, b0);
            }
        }
        __syncthreads();
    }
    float* Cs = S;   // [56][33]: rows 0..23 = ih gates, 32..55 = hh gates
    #pragma unroll
    for (int g2 = 0; g2 < 2; g2++) {
        int r0 = g2*32 + mt*16 + g, c0 = nt*8 + t4*2;
        Cs[r0*33 + c0] = acc[g2][0]; Cs[r0*33 + c0 + 1] = acc[g2][1];
        if (mt == 0) { Cs[(r0+8)*33 + c0] = acc[g2][2]; Cs[(r0+8)*33 + c0 + 1] = acc[g2][3]; }
    }
    __syncthreads();

    int jj = tid>>5, b = tid&31, j = j0 + jj;
    float xr = Cs[jj*33 + b]        + bih[j];
    float xz = Cs[(8+jj)*33 + b]    + bih[HSZ+j];
    float xn = Cs[(16+jj)*33 + b]   + bih[2*HSZ+j];
    float hr = Cs[(32+jj)*33 + b]   + bhh[j];
    float hz = Cs[(40+jj)*33 + b]   + bhh[HSZ+j];
    float hn = Cs[(48+jj)*33 + b]   + bhh[2*HSZ+j];
    float rr = 1.f/(1.f + expf(-(xr + hr)));
    float zz = 1.f/(1.f + expf(-(xz + hz)));
    float nn = tanhf(xn + rr*hn);
    float hp = __ldcg(h1o32 + (size_t)b*HSZ + j);
    float h = (1.f - zz)*nn + zz*hp;
    size_t o = (size_t)b*HSZ + j;
    w32[o] = h;
    float hi = tf32v(h);
    whi[o] = hi;
    wlo[o] = tf32v(h - hi);
    dest[o] = destHi ? hi : h;
}

__global__ __launch_bounds__(256) void rnn_persistent(
    const float* ebhh0, const float* ebih1, const float* ebhh1,
    const float* dbhh0, const float* dbih1, const float* dbhh1)
{
    extern __shared__ float S[];
    uint32_t s_base = (uint32_t)__cvta_generic_to_shared(S);
    int tid = threadIdx.x;
    int j0 = blockIdx.x*8;
    int sense = g_bar_sense;   // seed from persistent global (replay-safe)

    // zero initial hidden (parity 0) for this block's j slice
    {
        int jj = tid>>5, b = tid&31;
        size_t o = (size_t)b*HSZ + j0 + jj;
        g_h0_32[o]=0.f; g_h0_hi[o]=0.f; g_h0_lo[o]=0.f;
        g_h1_32[o]=0.f; g_h1_hi[o]=0.f; g_h1_lo[o]=0.f;
    }
    gbar(&sense);

    const float* eWhh0_hi = g_whi + 0*(size_t)WSZ; const float* eWhh0_lo = g_wlo + 0*(size_t)WSZ;
    const float* eWih1_hi = g_whi + 1*(size_t)WSZ; const float* eWih1_lo = g_wlo + 1*(size_t)WSZ;
    const float* eWhh1_hi = g_whi + 2*(size_t)WSZ; const float* eWhh1_lo = g_wlo + 2*(size_t)WSZ;
    const float* dWhh0_hi = g_whi + 3*(size_t)WSZ; const float* dWhh0_lo = g_wlo + 3*(size_t)WSZ;
    const float* dWih1_hi = g_whi + 4*(size_t)WSZ; const float* dWih1_lo = g_wlo + 4*(size_t)WSZ;
    const float* dWhh1_hi = g_whi + 5*(size_t)WSZ; const float* dWhh1_lo = g_wlo + 5*(size_t)WSZ;

    // ---- encoder ----
    for (int t = 0; t < SSZ; t++) {
        int rp = t & 1, wp = rp ^ 1;
        mma_phase_l0(S, s_base, eWhh0_hi, eWhh0_lo,
                     g_h0_hi + rp*BH, g_h0_lo + rp*BH, g_h0_32 + rp*BH,
                     g_gx_enc + (size_t)t*GXS, ebhh0,
                     g_h0_32 + wp*BH, g_h0_hi + wp*BH, g_h0_lo + wp*BH, tid, j0);
        gbar(&sense);
        mma_phase_l1(S, s_base,
                     eWih1_hi, eWih1_lo, eWhh1_hi, eWhh1_lo,
                     g_h0_hi + wp*BH, g_h0_lo + wp*BH,
                     g_h1_hi + rp*BH, g_h1_lo + rp*BH,
                     g_h1_32 + rp*BH, ebih1, ebhh1,
                     g_h1_32 + wp*BH, g_h1_hi + wp*BH, g_h1_lo + wp*BH,
                     g_enc_out_t + (size_t)t*BH, false, tid, j0);
        gbar(&sense);
    }
    // encoder final hidden at parity 0 (S even)

    // ---- decoder ----
    for (int t = 0; t < TSZ-1; t++) {
        int rp = t & 1, wp = rp ^ 1;
        const float* h0r32 = (t==0) ? g_h0_32 : g_dh0_32 + rp*BH;
        const float* h0rhi = (t==0) ? g_h0_hi : g_dh0_hi + rp*BH;
        const float* h0rlo = (t==0) ? g_h0_lo : g_dh0_lo + rp*BH;
        const float* h1r32 = (t==0) ? g_h1_32 : g_dh1_32 + rp*BH;
        const float* h1rhi = (t==0) ? g_h1_hi : g_dh1_hi + rp*BH;
        const float* h1rlo = (t==0) ? g_h1_lo : g_dh1_lo + rp*BH;

        mma_phase_l0(S, s_base, dWhh0_hi, dWhh0_lo,
                     h0rhi, h0rlo, h0r32,
                     g_gx_dec + (size_t)t*GXS, dbhh0,
                     g_dh0_32 + wp*BH, g_dh0_hi + wp*BH, g_dh0_lo + wp*BH, tid, j0);
        gbar(&sense);
        mma_phase_l1(S, s_base,
                     dWih1_hi, dWih1_lo, dWhh1_hi, dWhh1_lo,
                     g_dh0_hi + wp*BH, g_dh0_lo + wp*BH,
                     h1rhi, h1rlo, h1r32, dbih1, dbhh1,
                     g_dh1_32 + wp*BH, g_dh1_hi + wp*BH, g_dh1_lo + wp*BH,
                     g_h1_all + (size_t)t*BH, true, tid, j0);
        gbar(&sense);
    }
}

// ---------------- batched attention ----------------
__global__ __launch_bounds__(256) void attn_batched(
    const float* __restrict__ h1_all,
    const float* __restrict__ enc_out_t,
    const int*   __restrict__ src_tokens,
    float* __restrict__ ctx_all)
{
    int b = blockIdx.x, t = blockIdx.y;
    const float* h1t = h1_all + (size_t)t*BH;
    float* ctx = ctx_all + (size_t)t*BH;
    int w = threadIdx.x >> 5, lane = threadIdx.x & 31;
    __shared__ float sc[64];

    float4 q[8];
    #pragma unroll
    for (int c = 0; c < 8; c++)
        q[c] = *(const float4*)(h1t + (size_t)b*HSZ + c*128 + lane*4);

    #pragma unroll
    for (int i = 0; i < 8; i++) {
        int s = w*8 + i;
        const float* e = enc_out_t + ((size_t)s*BSZ + b)*HSZ;
        float acc = 0.f;
        #pragma unroll
        for (int c = 0; c < 8; c++) {
            float4 ev = *(const float4*)(e + c*128 + lane*4);
            acc += q[c].x*ev.x + q[c].y*ev.y + q[c].z*ev.z + q[c].w*ev.w;
        }
        #pragma unroll
        for (int off = 16; off; off >>= 1)
            acc += __shfl_xor_sync(0xffffffffu, acc, off);
        if (lane == 0)
            sc[s] = (src_tokens[s*BSZ + b] != PAD_IDX) ? acc : NEGV;
    }
    __syncthreads();

    if (w == 0) {
        float v0 = sc[lane], v1 = sc[lane+32];
        float m = fmaxf(v0, v1);
        #pragma unroll
        for (int off = 16; off; off >>= 1)
            m = fmaxf(m, __shfl_xor_sync(0xffffffffu, m, off));
        float e0 = expf(v0 - m), e1 = expf(v1 - m);
        float ssum = e0 + e1;
        #pragma unroll
        for (int off = 16; off; off >>= 1)
            ssum += __shfl_xor_sync(0xffffffffu, ssum, off);
        sc[lane]    = e0/ssum;
        sc[lane+32] = e1/ssum;
    }
    __syncthreads();

    float4 a4 = make_float4(0.f, 0.f, 0.f, 0.f);
    for (int s = 0; s < SSZ; s++) {
        float at = sc[s];
        float4 ev = *(const float4*)(enc_out_t + ((size_t)s*BSZ + b)*HSZ + threadIdx.x*4);
        a4.x += at*ev.x; a4.y += at*ev.y; a4.z += at*ev.z; a4.w += at*ev.w;
    }
    uint4 u = make_uint4(f2tf32(a4.x), f2tf32(a4.y), f2tf32(a4.z), f2tf32(a4.w));
    *(uint4*)(ctx + (size_t)b*HSZ + threadIdx.x*4) = u;
}

// ---------------- batched cc GEMM (tf32 mma) ----------------
#define CC_SMEM ((2*128*36 + 2*128*36)*4)
__global__ __launch_bounds__(256) void cc_mma(
    const float* __restrict__ h1a, const float* __restrict__ ctxa,
    const float* __restrict__ wc,  const float* __restrict__ bc,
    float* __restrict__ cc)
{
    extern __shared__ uint32_t sm[];
    uint32_t* As = sm;
    uint32_t* Bs = sm + 2*128*36;

    int tid = threadIdx.x, w = tid >> 5, lane = tid & 31;
    int g = lane >> 2, t4 = lane & 3;
    int warpM = w & 1, warpN = w >> 1;
    int mb = blockIdx.x * 128, nb = blockIdx.y * 128;

    uint32_t as_s = (uint32_t)__cvta_generic_to_shared(As);
    uint32_t bs_s = (uint32_t)__cvta_generic_to_shared(Bs);

    float acc[4][4][4];
    #pragma unroll
    for (int i = 0; i < 4; i++)
        #pragma unroll
        for (int jj = 0; jj < 4; jj++)
            #pragma unroll
            for (int k = 0; k < 4; k++) acc[i][jj][k] = 0.f;

    auto issue = [&](int ch) {
        int kc0 = ch*32, buf = ch & 1;
        uint32_t ao = as_s + buf*128*36*4;
        uint32_t bo2 = bs_s + buf*128*36*4;
        #pragma unroll
        for (int i = 0; i < 4; i++) {
            int idx = tid + i*256, r = idx >> 3, c = (idx & 7)*4;
            int k = kc0 + c;
            const float* src = (k < HSZ) ? (h1a + (size_t)(mb+r)*HSZ + k)
                                         : (ctxa + (size_t)(mb+r)*HSZ + (k - HSZ));
            cp16(ao + (r*36 + c)*4, src);
        }
        #pragma unroll
        for (int i = 0; i < 4; i++) {
            int idx = tid + i*256, r = idx >> 3, c = (idx & 7)*4;
            cp16(bo2 + (r*36 + c)*4, wc + (size_t)(nb+r)*(2*HSZ) + kc0 + c);
        }
        CP_COMMIT();
    };

    issue(0);
    for (int ch = 0; ch < 64; ch++) {
        if (ch < 63) { issue(ch+1); CP_WAIT(1); } else { CP_WAIT(0); }
        __syncthreads();
        int buf = ch & 1;
        const uint32_t* A0 = As + buf*128*36 + (warpM*64 + g)*36;
        const uint32_t* B0 = Bs + buf*128*36 + (warpN*32 + g)*36;
        #pragma unroll
        for (int ks = 0; ks < 4; ks++) {
            uint32_t a[4][4], b[4][2];
            #pragma unroll
            for (int mf = 0; mf < 4; mf++) {
                const uint32_t* ap = A0 + mf*16*36 + ks*8 + t4;
                a[mf][0] = ap[0]; a[mf][1] = ap[8*36]; a[mf][2] = ap[4]; a[mf][3] = ap[8*36+4];
            }
            #pragma unroll
            for (int nf = 0; nf < 4; nf++) {
                const uint32_t* bp = B0 + nf*8*36 + ks*8 + t4;
                b[nf][0] = bp[0]; b[nf][1] = bp[4];
            }
            #pragma unroll
            for (int mf = 0; mf < 4; mf++)
                #pragma unroll
                for (int nf = 0; nf < 4; nf++)
                    mma_tf32(acc[mf][nf], a[mf], b[nf]);
        }
        __syncthreads();
    }

    #pragma unroll
    for (int nf = 0; nf < 4; nf++) {
        int n = nb + warpN*32 + nf*8 + t4*2;
        float b0v = bc[n], b1v = bc[n+1];
        #pragma unroll
        for (int mf = 0; mf < 4; mf++) {
            int m_lo = mb + warpM*64 + mf*16 + g;
            int m_hi = m_lo + 8;
            if (m_lo < (TSZ-1)*BSZ) {
                cc[(size_t)m_lo*HSZ + n  ] = tf32v(tanhf(acc[mf][nf][0] + b0v));
                cc[(size_t)m_lo*HSZ + n+1] = tf32v(tanhf(acc[mf][nf][1] + b1v));
            }
            if (m_hi < (TSZ-1)*BSZ) {
                cc[(size_t)m_hi*HSZ + n  ] = tf32v(tanhf(acc[mf][nf][2] + b0v));
                cc[(size_t)m_hi*HSZ + n+1] = tf32v(tanhf(acc[mf][nf][3] + b1v));
            }
        }
    }
}

// ---------------- logits GEMM (tf32 mma) ----------------
#define LG_SMEM ((2*128*36 + 2*256*36)*4)
__global__ __launch_bounds__(256) void logits_mma(
    const float* __restrict__ cc, const float* __restrict__ wo,
    const float* __restrict__ bo, float* __restrict__ out)
{
    extern __shared__ uint32_t sm[];
    uint32_t* As = sm;
    uint32_t* Bs = sm + 2*128*36;

    int tid = threadIdx.x, w = tid >> 5, lane = tid & 31;
    int g = lane >> 2, t4 = lane & 3;
    int warpM = w & 1, warpN = w >> 1;
    int mb = blockIdx.x * 128, vb = blockIdx.y * 256;

    const float* Ag = cc + (size_t)mb*HSZ;
    const float* Bg = wo + (size_t)vb*HSZ;
    uint32_t as_s = (uint32_t)__cvta_generic_to_shared(As);
    uint32_t bs_s = (uint32_t)__cvta_generic_to_shared(Bs);

    float acc[4][8][4];
    #pragma unroll
    for (int i = 0; i < 4; i++)
        #pragma unroll
        for (int jj = 0; jj < 8; jj++)
            #pragma unroll
            for (int k = 0; k < 4; k++) acc[i][jj][k] = 0.f;

    {
        #pragma unroll
        for (int i = 0; i < 4; i++) {
            int idx = tid + i*256, r = idx >> 3, c = (idx & 7)*4;
            cp16(as_s + (r*36 + c)*4, Ag + (size_t)r*HSZ + c);
        }
        #pragma unroll
        for (int i = 0; i < 8; i++) {
            int idx = tid + i*256, r = idx >> 3, c = (idx & 7)*4;
            cp16(bs_s + (r*36 + c)*4, Bg + (size_t)r*HSZ + c);
        }
        CP_COMMIT();
    }

    for (int ch = 0; ch < 32; ch++) {
        if (ch < 31) {
            int kc0 = (ch+1)*32, buf = (ch+1) & 1;
            uint32_t ao = as_s + buf*128*36*4;
            uint32_t bo_s = bs_s + buf*256*36*4;
            #pragma unroll
            for (int i = 0; i < 4; i++) {
                int idx = tid + i*256, r = idx >> 3, c = (idx & 7)*4;
                cp16(ao + (r*36 + c)*4, Ag + (size_t)r*HSZ + kc0 + c);
            }
            #pragma unroll
            for (int i = 0; i < 8; i++) {
                int idx = tid + i*256, r = idx >> 3, c = (idx & 7)*4;
                cp16(bo_s + (r*36 + c)*4, Bg + (size_t)r*HSZ + kc0 + c);
            }
            CP_COMMIT();
            CP_WAIT(1);
        } else {
            CP_WAIT(0);
        }
        __syncthreads();

        int buf = ch & 1;
        const uint32_t* A0 = As + buf*128*36 + (warpM*64 + g)*36;
        const uint32_t* B0 = Bs + buf*256*36 + (warpN*64 + g)*36;

        #pragma unroll
        for (int ks = 0; ks < 4; ks++) {
            uint32_t a[4][4], b[8][2];
            #pragma unroll
            for (int mf = 0; mf < 4; mf++) {
                const uint32_t* ap = A0 + mf*16*36 + ks*8 + t4;
                a[mf][0] = ap[0]; a[mf][1] = ap[8*36]; a[mf][2] = ap[4]; a[mf][3] = ap[8*36+4];
            }
            #pragma unroll
            for (int nf = 0; nf < 8; nf++) {
                const uint32_t* bp = B0 + nf*8*36 + ks*8 + t4;
                b[nf][0] = bp[0]; b[nf][1] = bp[4];
            }
            #pragma unroll
            for (int mf = 0; mf < 4; mf++)
                #pragma unroll
                for (int nf = 0; nf < 8; nf++)
                    mma_tf32(acc[mf][nf], a[mf], b[nf]);
        }
        __syncthreads();
    }

    #pragma unroll
    for (int nf = 0; nf < 8; nf++) {
        int v = vb + warpN*64 + nf*8 + t4*2;
        float b0v = bo[v], b1v = bo[v+1];
        #pragma unroll
        for (int mf = 0; mf < 4; mf++) {
            int m_lo = mb + warpM*64 + mf*16 + g;
            int m_hi = m_lo + 8;
            if (m_lo < (TSZ-1)*BSZ) {
                out[(size_t)(m_lo + BSZ)*VSZ + v    ] = acc[mf][nf][0] + b0v;
                out[(size_t)(m_lo + BSZ)*VSZ + v + 1] = acc[mf][nf][1] + b1v;
            }
            if (m_hi < (TSZ-1)*BSZ) {
                out[(size_t)(m_hi + BSZ)*VSZ + v    ] = acc[mf][nf][2] + b0v;
                out[(size_t)(m_hi + BSZ)*VSZ + v + 1] = acc[mf][nf][3] + b1v;
            }
        }
    }
}

// ---------------- host ----------------
extern "C" void kernel_launch(void* const* d_in, const int* in_sizes, int n_in,
                              void* d_out, int out_size) {
    const int*   src_tokens = (const int*)  d_in[0];
    const int*   tgt_tokens = (const int*)  d_in[1];
    const float* enc_emb    = (const float*)d_in[2];
    const float* enc_Wih0   = (const float*)d_in[3];
    const float* enc_Whh0   = (const float*)d_in[4];
    const float* enc_bih0   = (const float*)d_in[5];
    const float* enc_bhh0   = (const float*)d_in[6];
    const float* enc_Wih1   = (const float*)d_in[7];
    const float* enc_Whh1   = (const float*)d_in[8];
    const float* enc_bih1   = (const float*)d_in[9];
    const float* enc_bhh1   = (const float*)d_in[10];
    const float* dec_emb    = (const float*)d_in[11];
    const float* dec_Wih0   = (const float*)d_in[12];
    const float* dec_Whh0   = (const float*)d_in[13];
    const float* dec_bih0   = (const float*)d_in[14];
    const float* dec_bhh0   = (const float*)d_in[15];
    const float* dec_Wih1   = (const float*)d_in[16];
    const float* dec_Whh1   = (const float*)d_in[17];
    const float* dec_bih1   = (const float*)d_in[18];
    const float* dec_bhh1   = (const float*)d_in[19];
    const float* Wc         = (const float*)d_in[20];
    const float* bc         = (const float*)d_in[21];
    const float* Wo         = (const float*)d_in[22];
    const float* bo         = (const float*)d_in[23];
    float* out = (float*)d_out;

    float *emb_src, *emb_dec, *gx_enc, *gx_dec, *enc_out_t;
    float *h1_all, *ctx_all, *cc_all, *wo_tf, *wc_tf;
    cudaGetSymbolAddress((void**)&emb_src,   g_emb_src);
    cudaGetSymbolAddress((void**)&emb_dec,   g_emb_dec);
    cudaGetSymbolAddress((void**)&gx_enc,    g_gx_enc);
    cudaGetSymbolAddress((void**)&gx_dec,    g_gx_dec);
    cudaGetSymbolAddress((void**)&enc_out_t, g_enc_out_t);
    cudaGetSymbolAddress((void**)&h1_all,    g_h1_all);
    cudaGetSymbolAddress((void**)&ctx_all,   g_ctx_all);
    cudaGetSymbolAddress((void**)&cc_all,    g_cc_all);
    cudaGetSymbolAddress((void**)&wo_tf,     g_wo_tf);
    cudaGetSymbolAddress((void**)&wc_tf,     g_wc_tf);

    cudaFuncSetAttribute(rnn_persistent, cudaFuncAttributeMaxDynamicSharedMemorySize, RNN_SMEM);
    cudaFuncSetAttribute(cc_mma,        cudaFuncAttributeMaxDynamicSharedMemorySize, CC_SMEM);
    cudaFuncSetAttribute(logits_mma,    cudaFuncAttributeMaxDynamicSharedMemorySize, LG_SMEM);

    // prep so that rnn_persistent is launch #6 (ncu -s 5 -c 1 profiles it)
    embed_kernel<<<(SSZ*BSZ*ESZ)/256, 256>>>(src_tokens, enc_emb, emb_src, SSZ*BSZ);          // 1
    embed_kernel<<<((TSZ-1)*BSZ*ESZ+255)/256, 256>>>(tgt_tokens, dec_emb, emb_dec, (TSZ-1)*BSZ); // 2
    proj_gemm<<<dim3(32, 48), 256>>>(emb_src, enc_Wih0, enc_bih0, gx_enc);                    // 3
    proj_gemm<<<dim3(32, 48), 256>>>(emb_dec, dec_Wih0, dec_bih0, gx_dec);                    // 4
    split_all<<<(6*(WSZ/4))/256, 256>>>(enc_Whh0, enc_Wih1, enc_Whh1,
                                        dec_Whh0, dec_Wih1, dec_Whh1);                        // 5

    // whole recurrence: ONE launch (3xtf32 tensor-core GEMMs)                                 // 6
    rnn_persistent<<<NBLK, 256, RNN_SMEM>>>(enc_bhh0, enc_bih1, enc_bhh1,
                                            dec_bhh0, dec_bih1, dec_bhh1);

    // epilogue
    zero_kernel<<<1024, 256>>>(out, BSZ*VSZ);
    cvt_tf32_kernel<<<(VSZ*HSZ/4)/256, 256>>>(Wo, wo_tf);
    cvt_tf32_kernel<<<(HSZ*2*HSZ/4)/256, 256>>>(Wc, wc_tf);
    attn_batched<<<dim3(BSZ, TSZ-1), 256>>>(h1_all, enc_out_t, src_tokens, ctx_all);
    cc_mma<<<dim3(16, 8), 256, CC_SMEM>>>(h1_all, ctx_all, wc_tf, bc, cc_all);
    logits_mma<<<dim3(16, 125), 256, LG_SMEM>>>(cc_all, wo_tf, bo, out);
}

// round 14
// speedup vs baseline: 1.4678x; 1.0751x over previous
#include <cuda_runtime.h>
#include <math.h>
#include <stdint.h>

#define VSZ 32000
#define ESZ 512
#define HSZ 1024
#define SSZ 64
#define TSZ 64
#define BSZ 32
#define BH  (BSZ*HSZ)          // 32768
#define GXS (3*HSZ*BSZ)
#define WSZ (3*HSZ*HSZ)
#define PAD_IDX 1
#define NEGV -100000.0f
#define NBLK 128

// smem layout for recurrent phases (floats), K-chunk = 64
#define TW2 68
#define OFF2_AHI 0
#define OFF2_ALO (64*TW2)
#define OFF2_XHI (128*TW2)
#define OFF2_XLO (192*TW2)
#define BUFF2 (256*TW2)            // 17408 floats
#define RNN_SMEM (2*BUFF2*4)       // 139264 B

// ---------------- device scratch ----------------
__device__ float g_emb_src[SSZ*BSZ*ESZ];        // tf32-rounded
__device__ float g_emb_dec[TSZ*BSZ*ESZ];        // tf32-rounded
__device__ float g_wih0_tf[2*3*HSZ*ESZ];        // [enc|dec] Wih0 tf32
__device__ float g_gx_enc[SSZ*GXS];             // [s][n][b] (+bih0)
__device__ float g_gx_dec[TSZ*GXS];
__device__ float g_enc_out_t[SSZ*BH];           // [s][b][h]
__device__ float g_h0_32[2*BH], g_h0_hi[2*BH], g_h0_lo[2*BH];
__device__ float g_h1_32[2*BH], g_h1_hi[2*BH], g_h1_lo[2*BH];
__device__ float g_dh0_32[2*BH], g_dh0_hi[2*BH], g_dh0_lo[2*BH];
__device__ float g_dh1_32[2*BH], g_dh1_hi[2*BH], g_dh1_lo[2*BH];
__device__ float g_h1_all[TSZ*BH];
__device__ float g_ctx_all[TSZ*BH];
__device__ float g_cc_all[TSZ*BH];
__device__ float g_wo_tf[VSZ*HSZ];
__device__ float g_wc_tf[HSZ*2*HSZ];
__device__ float g_whi[6*WSZ];
__device__ float g_wlo[6*WSZ];
__device__ int           g_bar_cnt;
__device__ volatile int  g_bar_sense;

// ---------------- helpers ----------------
__device__ __forceinline__ uint32_t f2tf32(float f) {
    uint32_t u;
    asm("cvt.rna.tf32.f32 %0, %1;" : "=r"(u) : "f"(f));
    return u;
}
__device__ __forceinline__ float tf32v(float f) { return __uint_as_float(f2tf32(f)); }
__device__ __forceinline__ void cp16(uint32_t s, const void* g) {
    asm volatile("cp.async.cg.shared.global [%0], [%1], 16;" :: "r"(s), "l"(g));
}
#define CP_COMMIT() asm volatile("cp.async.commit_group;" ::: "memory")
#define CP_WAIT(N)  asm volatile("cp.async.wait_group %0;" :: "n"(N) : "memory")

__device__ __forceinline__ void mma_tf32(float* c, const uint32_t* a, const uint32_t* b) {
    asm volatile(
        "mma.sync.aligned.m16n8k8.row.col.f32.tf32.tf32.f32 "
        "{%0,%1,%2,%3},{%4,%5,%6,%7},{%8,%9},{%0,%1,%2,%3};"
        : "+f"(c[0]), "+f"(c[1]), "+f"(c[2]), "+f"(c[3])
        : "r"(a[0]), "r"(a[1]), "r"(a[2]), "r"(a[3]), "r"(b[0]), "r"(b[1]));
}

// replay-safe global barrier (sense seeded from the persistent global)
__device__ __forceinline__ void gbar(int* sense) {
    __syncthreads();
    if (threadIdx.x == 0) {
        __threadfence();
        int s = (*sense ^= 1);
        if (atomicAdd(&g_bar_cnt, 1) == NBLK - 1) {
            atomicExch(&g_bar_cnt, 0);
            __threadfence();
            g_bar_sense = s;
        } else {
            while (g_bar_sense != s) __nanosleep(32);
        }
    }
    __syncthreads();
}

// ---------------- utility kernels ----------------
__global__ void zero_kernel(float* p, int n) {
    for (int i = blockIdx.x*blockDim.x + threadIdx.x; i < n; i += gridDim.x*blockDim.x)
        p[i] = 0.f;
}
__global__ void cvt_tf32_kernel(const float* __restrict__ in, float* __restrict__ out) {
    int i = blockIdx.x*256 + threadIdx.x;
    float4 v = ((const float4*)in)[i];
    uint4 u = make_uint4(f2tf32(v.x), f2tf32(v.y), f2tf32(v.z), f2tf32(v.w));
    ((uint4*)out)[i] = u;
}
// fused: convert both Wih0 matrices into g_wih0_tf
__global__ void cvt2_wih0(const float* __restrict__ a, const float* __restrict__ b) {
    const int N4 = (3*HSZ*ESZ)/4;
    int i = blockIdx.x*256 + threadIdx.x;     // 0 .. 2*N4-1
    const float* src = (i < N4) ? a : b;
    int k = (i < N4) ? i : i - N4;
    float4 v = ((const float4*)src)[k];
    uint4 u = make_uint4(f2tf32(v.x), f2tf32(v.y), f2tf32(v.z), f2tf32(v.w));
    ((uint4*)g_wih0_tf)[i] = u;
}
// embed + tf32 round
__global__ void embed_kernel(const int* __restrict__ tok,
                             const float* __restrict__ emb,
                             float* __restrict__ out, int rows) {
    int idx = blockIdx.x*256 + threadIdx.x;
    if (idx >= rows*ESZ) return;
    int e = idx & (ESZ-1);
    int m = idx >> 9;
    out[idx] = tf32v(emb[(size_t)tok[m]*ESZ + e]);
}
__global__ void split_all(const float* w0, const float* w1, const float* w2,
                          const float* w3, const float* w4, const float* w5) {
    const int N4 = WSZ/4;
    int idx = blockIdx.x*256 + threadIdx.x;
    int m = idx / N4, i = idx - m*N4;
    const float* w = m==0?w0: m==1?w1: m==2?w2: m==3?w3: m==4?w4: w5;
    float4 v = ((const float4*)w)[i];
    float4 hi, lo;
    hi.x = tf32v(v.x); lo.x = tf32v(v.x - hi.x);
    hi.y = tf32v(v.y); lo.y = tf32v(v.y - hi.y);
    hi.z = tf32v(v.z); lo.z = tf32v(v.z - hi.z);
    hi.w = tf32v(v.w); lo.w = tf32v(v.w - hi.w);
    ((float4*)(g_whi + (size_t)m*WSZ))[i] = hi;
    ((float4*)(g_wlo + (size_t)m*WSZ))[i] = lo;
}

// ---------------- input projection via tf32 mma ----------------
// gx[t][n][b] = W[n][:512]·emb[m][:512] + bih[n];  tile 128m x 128n, K=512.
// blockIdx.z: 0 = encoder, 1 = decoder.
#define PJ_SMEM ((2*128*36 + 2*128*36)*4)
__global__ __launch_bounds__(256) void proj_mma(
    const float* __restrict__ Ae, const float* __restrict__ Ad,   // emb tf32
    const float* __restrict__ biasE, const float* __restrict__ biasD,
    float* __restrict__ gxE, float* __restrict__ gxD,
    int rowsE, int rowsD)
{
    extern __shared__ uint32_t sm[];
    uint32_t* As = sm;
    uint32_t* Bs = sm + 2*128*36;

    int z = blockIdx.z;
    const float* Am  = z ? Ad : Ae;
    const float* Wt  = g_wih0_tf + (size_t)z*3*HSZ*ESZ;
    const float* bias = z ? biasD : biasE;
    float* gx = z ? gxD : gxE;
    int rows = z ? rowsD : rowsE;

    int tid = threadIdx.x, w = tid >> 5, lane = tid & 31;
    int g = lane >> 2, t4 = lane & 3;
    int warpM = w & 1, warpN = w >> 1;
    int mb = blockIdx.x * 128, nb = blockIdx.y * 128;

    uint32_t as_s = (uint32_t)__cvta_generic_to_shared(As);
    uint32_t bs_s = (uint32_t)__cvta_generic_to_shared(Bs);

    float acc[4][4][4];
    #pragma unroll
    for (int i = 0; i < 4; i++)
        #pragma unroll
        for (int jj = 0; jj < 4; jj++)
            #pragma unroll
            for (int k = 0; k < 4; k++) acc[i][jj][k] = 0.f;

    auto issue = [&](int ch) {
        int kc0 = ch*32, buf = ch & 1;
        uint32_t ao = as_s + buf*128*36*4;
        uint32_t bo2 = bs_s + buf*128*36*4;
        #pragma unroll
        for (int i = 0; i < 4; i++) {
            int idx = tid + i*256, r = idx >> 3, c = (idx & 7)*4;
            cp16(ao + (r*36 + c)*4, Am + (size_t)(mb+r)*ESZ + kc0 + c);
        }
        #pragma unroll
        for (int i = 0; i < 4; i++) {
            int idx = tid + i*256, r = idx >> 3, c = (idx & 7)*4;
            cp16(bo2 + (r*36 + c)*4, Wt + (size_t)(nb+r)*ESZ + kc0 + c);
        }
        CP_COMMIT();
    };

    issue(0);
    for (int ch = 0; ch < 16; ch++) {
        if (ch < 15) { issue(ch+1); CP_WAIT(1); } else { CP_WAIT(0); }
        __syncthreads();
        int buf = ch & 1;
        const uint32_t* A0 = As + buf*128*36 + (warpM*64 + g)*36;
        const uint32_t* B0 = Bs + buf*128*36 + (warpN*32 + g)*36;
        #pragma unroll
        for (int ks = 0; ks < 4; ks++) {
            uint32_t a[4][4], b[4][2];
            #pragma unroll
            for (int mf = 0; mf < 4; mf++) {
                const uint32_t* ap = A0 + mf*16*36 + ks*8 + t4;
                a[mf][0] = ap[0]; a[mf][1] = ap[8*36]; a[mf][2] = ap[4]; a[mf][3] = ap[8*36+4];
            }
            #pragma unroll
            for (int nf = 0; nf < 4; nf++) {
                const uint32_t* bp = B0 + nf*8*36 + ks*8 + t4;
                b[nf][0] = bp[0]; b[nf][1] = bp[4];
            }
            #pragma unroll
            for (int mf = 0; mf < 4; mf++)
                #pragma unroll
                for (int nf = 0; nf < 4; nf++)
                    mma_tf32(acc[mf][nf], a[mf], b[nf]);
        }
        __syncthreads();
    }

    #pragma unroll
    for (int nf = 0; nf < 4; nf++) {
        int n = nb + warpN*32 + nf*8 + t4*2;
        float b0v = bias[n], b1v = bias[n+1];
        #pragma unroll
        for (int mf = 0; mf < 4; mf++) {
            int m_lo = mb + warpM*64 + mf*16 + g;
            int m_hi = m_lo + 8;
            if (m_lo < rows) {
                int t = m_lo >> 5, b = m_lo & 31;
                gx[(size_t)t*GXS + (size_t)n*BSZ + b]     = acc[mf][nf][0] + b0v;
                gx[(size_t)t*GXS + (size_t)(n+1)*BSZ + b] = acc[mf][nf][1] + b1v;
            }
            if (m_hi < rows) {
                int t = m_hi >> 5, b = m_hi & 31;
                gx[(size_t)t*GXS + (size_t)n*BSZ + b]     = acc[mf][nf][2] + b0v;
                gx[(size_t)t*GXS + (size_t)(n+1)*BSZ + b] = acc[mf][nf][3] + b1v;
            }
        }
    }
}

// ---------------- persistent recurrent phases (3xtf32 mma, K-chunk 64) ----
__device__ __forceinline__ void mma_phase_l0(
    float* S, uint32_t s_base,
    const float* Ahi, const float* Alo,
    const float* Xhi, const float* Xlo, const float* hold32,
    const float* gx, const float* __restrict__ bhh,
    float* w32, float* whi, float* wlo,
    int tid, int j0)
{
    int w = tid>>5, lane = tid&31;
    int mt = (w>>2)&1, nt = w&3, g = lane>>2, t4 = lane&3;
    float acc[4] = {0.f,0.f,0.f,0.f};

    auto issue = [&](int ch) {
        int kc0 = ch*64, buf = ch&1;
        uint32_t base = s_base + buf*BUFF2*4;
        #pragma unroll
        for (int i = 0; i < 2; i++) {
            int idx = tid + i*256;
            int r = idx >> 4, c = (idx & 15)*4;   // r 0..31, c 0..60
            int gate = r>>3, jj2 = r&7;
            size_t grow = (size_t)((gate<3 ? gate*HSZ : 0) + j0 + jj2);
            cp16(base + (OFF2_AHI + r*TW2 + c)*4, Ahi + grow*HSZ + kc0 + c);
            cp16(base + (OFF2_ALO + r*TW2 + c)*4, Alo + grow*HSZ + kc0 + c);
            cp16(base + (OFF2_XHI + r*TW2 + c)*4, Xhi + (size_t)r*HSZ + kc0 + c);
            cp16(base + (OFF2_XLO + r*TW2 + c)*4, Xlo + (size_t)r*HSZ + kc0 + c);
        }
        CP_COMMIT();
    };

    issue(0);
    for (int ch = 0; ch < 16; ch++) {
        if (ch < 15) { issue(ch+1); CP_WAIT(1); } else { CP_WAIT(0); }
        __syncthreads();
        const uint32_t* B = (const uint32_t*)S + (ch&1)*BUFF2;
        int arow = mt*16 + g, xrow = nt*8 + g;
        #pragma unroll
        for (int ks = 0; ks < 8; ks++) {
            const uint32_t* ah = B + OFF2_AHI + arow*TW2 + ks*8 + t4;
            const uint32_t* al = B + OFF2_ALO + arow*TW2 + ks*8 + t4;
            const uint32_t* bh = B + OFF2_XHI + xrow*TW2 + ks*8 + t4;
            const uint32_t* bl = B + OFF2_XLO + xrow*TW2 + ks*8 + t4;
            uint32_t a0[4] = {ah[0], ah[8*TW2], ah[4], ah[8*TW2+4]};
            uint32_t a1[4] = {al[0], al[8*TW2], al[4], al[8*TW2+4]};
            uint32_t b0[2] = {bh[0], bh[4]};
            uint32_t b1[2] = {bl[0], bl[4]};
            mma_tf32(acc, a0, b0);
            mma_tf32(acc, a0, b1);
            mma_tf32(acc, a1, b0);
        }
        __syncthreads();
    }
    float* Cs = S;   // [32][33], rows 0..23 valid
    int r0 = mt*16 + g, c0 = nt*8 + t4*2;
    Cs[r0*33 + c0] = acc[0]; Cs[r0*33 + c0 + 1] = acc[1];
    if (mt == 0) { Cs[(r0+8)*33 + c0] = acc[2]; Cs[(r0+8)*33 + c0 + 1] = acc[3]; }
    __syncthreads();

    int jj = tid>>5, b = tid&31, j = j0 + jj;
    float ghr = Cs[jj*33 + b]      + bhh[j];
    float ghz = Cs[(8+jj)*33 + b]  + bhh[HSZ+j];
    float ghn = Cs[(16+jj)*33 + b] + bhh[2*HSZ+j];
    float gr = gx[(size_t)j*BSZ + b]         + ghr;
    float gz = gx[(size_t)(HSZ+j)*BSZ + b]   + ghz;
    float rr = 1.f/(1.f + expf(-gr));
    float zz = 1.f/(1.f + expf(-gz));
    float nn = tanhf(gx[(size_t)(2*HSZ+j)*BSZ + b] + rr*ghn);
    float hp = __ldcg(hold32 + (size_t)b*HSZ + j);
    float h = (1.f - zz)*nn + zz*hp;
    size_t o = (size_t)b*HSZ + j;
    w32[o] = h;
    float hi = tf32v(h);
    whi[o] = hi;
    wlo[o] = tf32v(h - hi);
}

__device__ __forceinline__ void mma_phase_l1(
    float* S, uint32_t s_base,
    const float* A0hi, const float* A0lo,
    const float* A1hi, const float* A1lo,
    const float* X0hi, const float* X0lo,
    const float* X1hi, const float* X1lo,
    const float* h1o32,
    const float* __restrict__ bih, const float* __restrict__ bhh,
    float* w32, float* whi, float* wlo,
    float* dest, bool destHi,
    int tid, int j0)
{
    int w = tid>>5, lane = tid&31;
    int mt = (w>>2)&1, nt = w&3, g = lane>>2, t4 = lane&3;
    float acc[2][4] = {{0.f,0.f,0.f,0.f},{0.f,0.f,0.f,0.f}};

    auto issue = [&](int ch) {
        int kc0 = ch*64, buf = ch&1;
        uint32_t base = s_base + buf*BUFF2*4;
        #pragma unroll
        for (int i = 0; i < 4; i++) {
            int idx = tid + i*256;
            int r = idx >> 4, c = (idx & 15)*4;   // r 0..63
            int rl = r & 31;
            int gate = rl>>3, jj2 = rl&7;
            size_t grow = (size_t)((gate<3 ? gate*HSZ : 0) + j0 + jj2);
            const float* Ah = (r < 32) ? A0hi : A1hi;
            const float* Al = (r < 32) ? A0lo : A1lo;
            const float* Xh = (r < 32) ? X0hi : X1hi;
            const float* Xl = (r < 32) ? X0lo : X1lo;
            cp16(base + (OFF2_AHI + r*TW2 + c)*4, Ah + grow*HSZ + kc0 + c);
            cp16(base + (OFF2_ALO + r*TW2 + c)*4, Al + grow*HSZ + kc0 + c);
            cp16(base + (OFF2_XHI + r*TW2 + c)*4, Xh + (size_t)rl*HSZ + kc0 + c);
            cp16(base + (OFF2_XLO + r*TW2 + c)*4, Xl + (size_t)rl*HSZ + kc0 + c);
        }
        CP_COMMIT();
    };

    issue(0);
    for (int ch = 0; ch < 16; ch++) {
        if (ch < 15) { issue(ch+1); CP_WAIT(1); } else { CP_WAIT(0); }
        __syncthreads();
        const uint32_t* B = (const uint32_t*)S + (ch&1)*BUFF2;
        #pragma unroll
        for (int g2 = 0; g2 < 2; g2++) {
            int arow = g2*32 + mt*16 + g, xrow = g2*32 + nt*8 + g;
            #pragma unroll
            for (int ks = 0; ks < 8; ks++) {
                const uint32_t* ah = B + OFF2_AHI + arow*TW2 + ks*8 + t4;
                const uint32_t* al = B + OFF2_ALO + arow*TW2 + ks*8 + t4;
                const uint32_t* bh = B + OFF2_XHI + xrow*TW2 + ks*8 + t4;
                const uint32_t* bl = B + OFF2_XLO + xrow*TW2 + ks*8 + t4;
                uint32_t a0[4] = {ah[0], ah[8*TW2], ah[4], ah[8*TW2+4]};
                uint32_t a1[4] = {al[0], al[8*TW2], al[4], al[8*TW2+4]};
                uint32_t b0[2] = {bh[0], bh[4]};
                uint32_t b1[2] = {bl[0], bl[4]};
                mma_tf32(acc[g2], a0, b0);
                mma_tf32(acc[g2], a0, b1);
                mma_tf32(acc[g2], a1, b0);
            }
        }
        __syncthreads();
    }
    float* Cs = S;   // [56][33]
    #pragma unroll
    for (int g2 = 0; g2 < 2; g2++) {
        int r0 = g2*32 + mt*16 + g, c0 = nt*8 + t4*2;
        Cs[r0*33 + c0] = acc[g2][0]; Cs[r0*33 + c0 + 1] = acc[g2][1];
        if (mt == 0) { Cs[(r0+8)*33 + c0] = acc[g2][2]; Cs[(r0+8)*33 + c0 + 1] = acc[g2][3]; }
    }
    __syncthreads();

    int jj = tid>>5, b = tid&31, j = j0 + jj;
    float xr = Cs[jj*33 + b]        + bih[j];
    float xz = Cs[(8+jj)*33 + b]    + bih[HSZ+j];
    float xn = Cs[(16+jj)*33 + b]   + bih[2*HSZ+j];
    float hr = Cs[(32+jj)*33 + b]   + bhh[j];
    float hz = Cs[(40+jj)*33 + b]   + bhh[HSZ+j];
    float hn = Cs[(48+jj)*33 + b]   + bhh[2*HSZ+j];
    float rr = 1.f/(1.f + expf(-(xr + hr)));
    float zz = 1.f/(1.f + expf(-(xz + hz)));
    float nn = tanhf(xn + rr*hn);
    float hp = __ldcg(h1o32 + (size_t)b*HSZ + j);
    float h = (1.f - zz)*nn + zz*hp;
    size_t o = (size_t)b*HSZ + j;
    w32[o] = h;
    float hi = tf32v(h);
    whi[o] = hi;
    wlo[o] = tf32v(h - hi);
    dest[o] = destHi ? hi : h;
}

__global__ __launch_bounds__(256) void rnn_persistent(
    const float* ebhh0, const float* ebih1, const float* ebhh1,
    const float* dbhh0, const float* dbih1, const float* dbhh1)
{
    extern __shared__ float S[];
    uint32_t s_base = (uint32_t)__cvta_generic_to_shared(S);
    int tid = threadIdx.x;
    int j0 = blockIdx.x*8;
    int sense = g_bar_sense;

    {
        int jj = tid>>5, b = tid&31;
        size_t o = (size_t)b*HSZ + j0 + jj;
        g_h0_32[o]=0.f; g_h0_hi[o]=0.f; g_h0_lo[o]=0.f;
        g_h1_32[o]=0.f; g_h1_hi[o]=0.f; g_h1_lo[o]=0.f;
    }
    gbar(&sense);

    const float* eWhh0_hi = g_whi + 0*(size_t)WSZ; const float* eWhh0_lo = g_wlo + 0*(size_t)WSZ;
    const float* eWih1_hi = g_whi + 1*(size_t)WSZ; const float* eWih1_lo = g_wlo + 1*(size_t)WSZ;
    const float* eWhh1_hi = g_whi + 2*(size_t)WSZ; const float* eWhh1_lo = g_wlo + 2*(size_t)WSZ;
    const float* dWhh0_hi = g_whi + 3*(size_t)WSZ; const float* dWhh0_lo = g_wlo + 3*(size_t)WSZ;
    const float* dWih1_hi = g_whi + 4*(size_t)WSZ; const float* dWih1_lo = g_wlo + 4*(size_t)WSZ;
    const float* dWhh1_hi = g_whi + 5*(size_t)WSZ; const float* dWhh1_lo = g_wlo + 5*(size_t)WSZ;

    for (int t = 0; t < SSZ; t++) {
        int rp = t & 1, wp = rp ^ 1;
        mma_phase_l0(S, s_base, eWhh0_hi, eWhh0_lo,
                     g_h0_hi + rp*BH, g_h0_lo + rp*BH, g_h0_32 + rp*BH,
                     g_gx_enc + (size_t)t*GXS, ebhh0,
                     g_h0_32 + wp*BH, g_h0_hi + wp*BH, g_h0_lo + wp*BH, tid, j0);
        gbar(&sense);
        mma_phase_l1(S, s_base,
                     eWih1_hi, eWih1_lo, eWhh1_hi, eWhh1_lo,
                     g_h0_hi + wp*BH, g_h0_lo + wp*BH,
                     g_h1_hi + rp*BH, g_h1_lo + rp*BH,
                     g_h1_32 + rp*BH, ebih1, ebhh1,
                     g_h1_32 + wp*BH, g_h1_hi + wp*BH, g_h1_lo + wp*BH,
                     g_enc_out_t + (size_t)t*BH, false, tid, j0);
        gbar(&sense);
    }

    for (int t = 0; t < TSZ-1; t++) {
        int rp = t & 1, wp = rp ^ 1;
        const float* h0r32 = (t==0) ? g_h0_32 : g_dh0_32 + rp*BH;
        const float* h0rhi = (t==0) ? g_h0_hi : g_dh0_hi + rp*BH;
        const float* h0rlo = (t==0) ? g_h0_lo : g_dh0_lo + rp*BH;
        const float* h1r32 = (t==0) ? g_h1_32 : g_dh1_32 + rp*BH;
        const float* h1rhi = (t==0) ? g_h1_hi : g_dh1_hi + rp*BH;
        const float* h1rlo = (t==0) ? g_h1_lo : g_dh1_lo + rp*BH;

        mma_phase_l0(S, s_base, dWhh0_hi, dWhh0_lo,
                     h0rhi, h0rlo, h0r32,
                     g_gx_dec + (size_t)t*GXS, dbhh0,
                     g_dh0_32 + wp*BH, g_dh0_hi + wp*BH, g_dh0_lo + wp*BH, tid, j0);
        gbar(&sense);
        mma_phase_l1(S, s_base,
                     dWih1_hi, dWih1_lo, dWhh1_hi, dWhh1_lo,
                     g_dh0_hi + wp*BH, g_dh0_lo + wp*BH,
                     h1rhi, h1rlo, h1r32, dbih1, dbhh1,
                     g_dh1_32 + wp*BH, g_dh1_hi + wp*BH, g_dh1_lo + wp*BH,
                     g_h1_all + (size_t)t*BH, true, tid, j0);
        gbar(&sense);
    }
}

// ---------------- batched attention ----------------
__global__ __launch_bounds__(256) void attn_batched(
    const float* __restrict__ h1_all,
    const float* __restrict__ enc_out_t,
    const int*   __restrict__ src_tokens,
    float* __restrict__ ctx_all)
{
    int b = blockIdx.x, t = blockIdx.y;
    const float* h1t = h1_all + (size_t)t*BH;
    float* ctx = ctx_all + (size_t)t*BH;
    int w = threadIdx.x >> 5, lane = threadIdx.x & 31;
    __shared__ float sc[64];

    float4 q[8];
    #pragma unroll
    for (int c = 0; c < 8; c++)
        q[c] = *(const float4*)(h1t + (size_t)b*HSZ + c*128 + lane*4);

    #pragma unroll
    for (int i = 0; i < 8; i++) {
        int s = w*8 + i;
        const float* e = enc_out_t + ((size_t)s*BSZ + b)*HSZ;
        float acc = 0.f;
        #pragma unroll
        for (int c = 0; c < 8; c++) {
            float4 ev = *(const float4*)(e + c*128 + lane*4);
            acc += q[c].x*ev.x + q[c].y*ev.y + q[c].z*ev.z + q[c].w*ev.w;
        }
        #pragma unroll
        for (int off = 16; off; off >>= 1)
            acc += __shfl_xor_sync(0xffffffffu, acc, off);
        if (lane == 0)
            sc[s] = (src_tokens[s*BSZ + b] != PAD_IDX) ? acc : NEGV;
    }
    __syncthreads();

    if (w == 0) {
        float v0 = sc[lane], v1 = sc[lane+32];
        float m = fmaxf(v0, v1);
        #pragma unroll
        for (int off = 16; off; off >>= 1)
            m = fmaxf(m, __shfl_xor_sync(0xffffffffu, m, off));
        float e0 = expf(v0 - m), e1 = expf(v1 - m);
        float ssum = e0 + e1;
        #pragma unroll
        for (int off = 16; off; off >>= 1)
            ssum += __shfl_xor_sync(0xffffffffu, ssum, off);
        sc[lane]    = e0/ssum;
        sc[lane+32] = e1/ssum;
    }
    __syncthreads();

    float4 a4 = make_float4(0.f, 0.f, 0.f, 0.f);
    for (int s = 0; s < SSZ; s++) {
        float at = sc[s];
        float4 ev = *(const float4*)(enc_out_t + ((size_t)s*BSZ + b)*HSZ + threadIdx.x*4);
        a4.x += at*ev.x; a4.y += at*ev.y; a4.z += at*ev.z; a4.w += at*ev.w;
    }
    uint4 u = make_uint4(f2tf32(a4.x), f2tf32(a4.y), f2tf32(a4.z), f2tf32(a4.w));
    *(uint4*)(ctx + (size_t)b*HSZ + threadIdx.x*4) = u;
}

// ---------------- batched cc GEMM (tf32 mma) ----------------
#define CC_SMEM ((2*128*36 + 2*128*36)*4)
__global__ __launch_bounds__(256) void cc_mma(
    const float* __restrict__ h1a, const float* __restrict__ ctxa,
    const float* __restrict__ wc,  const float* __restrict__ bc,
    float* __restrict__ cc)
{
    extern __shared__ uint32_t sm[];
    uint32_t* As = sm;
    uint32_t* Bs = sm + 2*128*36;

    int tid = threadIdx.x, w = tid >> 5, lane = tid & 31;
    int g = lane >> 2, t4 = lane & 3;
    int warpM = w & 1, warpN = w >> 1;
    int mb = blockIdx.x * 128, nb = blockIdx.y * 128;

    uint32_t as_s = (uint32_t)__cvta_generic_to_shared(As);
    uint32_t bs_s = (uint32_t)__cvta_generic_to_shared(Bs);

    float acc[4][4][4];
    #pragma unroll
    for (int i = 0; i < 4; i++)
        #pragma unroll
        for (int jj = 0; jj < 4; jj++)
            #pragma unroll
            for (int k = 0; k < 4; k++) acc[i][jj][k] = 0.f;

    auto issue = [&](int ch) {
        int kc0 = ch*32, buf = ch & 1;
        uint32_t ao = as_s + buf*128*36*4;
        uint32_t bo2 = bs_s + buf*128*36*4;
        #pragma unroll
        for (int i = 0; i < 4; i++) {
            int idx = tid + i*256, r = idx >> 3, c = (idx & 7)*4;
            int k = kc0 + c;
            const float* src = (k < HSZ) ? (h1a + (size_t)(mb+r)*HSZ + k)
                                         : (ctxa + (size_t)(mb+r)*HSZ + (k - HSZ));
            cp16(ao + (r*36 + c)*4, src);
        }
        #pragma unroll
        for (int i = 0; i < 4; i++) {
            int idx = tid + i*256, r = idx >> 3, c = (idx & 7)*4;
            cp16(bo2 + (r*36 + c)*4, wc + (size_t)(nb+r)*(2*HSZ) + kc0 + c);
        }
        CP_COMMIT();
    };

    issue(0);
    for (int ch = 0; ch < 64; ch++) {
        if (ch < 63) { issue(ch+1); CP_WAIT(1); } else { CP_WAIT(0); }
        __syncthreads();
        int buf = ch & 1;
        const uint32_t* A0 = As + buf*128*36 + (warpM*64 + g)*36;
        const uint32_t* B0 = Bs + buf*128*36 + (warpN*32 + g)*36;
        #pragma unroll
        for (int ks = 0; ks < 4; ks++) {
            uint32_t a[4][4], b[4][2];
            #pragma unroll
            for (int mf = 0; mf < 4; mf++) {
                const uint32_t* ap = A0 + mf*16*36 + ks*8 + t4;
                a[mf][0] = ap[0]; a[mf][1] = ap[8*36]; a[mf][2] = ap[4]; a[mf][3] = ap[8*36+4];
            }
            #pragma unroll
            for (int nf = 0; nf < 4; nf++) {
                const uint32_t* bp = B0 + nf*8*36 + ks*8 + t4;
                b[nf][0] = bp[0]; b[nf][1] = bp[4];
            }
            #pragma unroll
            for (int mf = 0; mf < 4; mf++)
                #pragma unroll
                for (int nf = 0; nf < 4; nf++)
                    mma_tf32(acc[mf][nf], a[mf], b[nf]);
        }
        __syncthreads();
    }

    #pragma unroll
    for (int nf = 0; nf < 4; nf++) {
        int n = nb + warpN*32 + nf*8 + t4*2;
        float b0v = bc[n], b1v = bc[n+1];
        #pragma unroll
        for (int mf = 0; mf < 4; mf++) {
            int m_lo = mb + warpM*64 + mf*16 + g;
            int m_hi = m_lo + 8;
            if (m_lo < (TSZ-1)*BSZ) {
                cc[(size_t)m_lo*HSZ + n  ] = tf32v(tanhf(acc[mf][nf][0] + b0v));
                cc[(size_t)m_lo*HSZ + n+1] = tf32v(tanhf(acc[mf][nf][1] + b1v));
            }
            if (m_hi < (TSZ-1)*BSZ) {
                cc[(size_t)m_hi*HSZ + n  ] = tf32v(tanhf(acc[mf][nf][2] + b0v));
                cc[(size_t)m_hi*HSZ + n+1] = tf32v(tanhf(acc[mf][nf][3] + b1v));
            }
        }
    }
}

// ---------------- logits GEMM (tf32 mma) ----------------
#define LG_SMEM ((2*128*36 + 2*256*36)*4)
__global__ __launch_bounds__(256) void logits_mma(
    const float* __restrict__ cc, const float* __restrict__ wo,
    const float* __restrict__ bo, float* __restrict__ out)
{
    extern __shared__ uint32_t sm[];
    uint32_t* As = sm;
    uint32_t* Bs = sm + 2*128*36;

    int tid = threadIdx.x, w = tid >> 5, lane = tid & 31;
    int g = lane >> 2, t4 = lane & 3;
    int warpM = w & 1, warpN = w >> 1;
    int mb = blockIdx.x * 128, vb = blockIdx.y * 256;

    const float* Ag = cc + (size_t)mb*HSZ;
    const float* Bg = wo + (size_t)vb*HSZ;
    uint32_t as_s = (uint32_t)__cvta_generic_to_shared(As);
    uint32_t bs_s = (uint32_t)__cvta_generic_to_shared(Bs);

    float acc[4][8][4];
    #pragma unroll
    for (int i = 0; i < 4; i++)
        #pragma unroll
        for (int jj = 0; jj < 8; jj++)
            #pragma unroll
            for (int k = 0; k < 4; k++) acc[i][jj][k] = 0.f;

    {
        #pragma unroll
        for (int i = 0; i < 4; i++) {
            int idx = tid + i*256, r = idx >> 3, c = (idx & 7)*4;
            cp16(as_s + (r*36 + c)*4, Ag + (size_t)r*HSZ + c);
        }
        #pragma unroll
        for (int i = 0; i < 8; i++) {
            int idx = tid + i*256, r = idx >> 3, c = (idx & 7)*4;
            cp16(bs_s + (r*36 + c)*4, Bg + (size_t)r*HSZ + c);
        }
        CP_COMMIT();
    }

    for (int ch = 0; ch < 32; ch++) {
        if (ch < 31) {
            int kc0 = (ch+1)*32, buf = (ch+1) & 1;
            uint32_t ao = as_s + buf*128*36*4;
            uint32_t bo_s = bs_s + buf*256*36*4;
            #pragma unroll
            for (int i = 0; i < 4; i++) {
                int idx = tid + i*256, r = idx >> 3, c = (idx & 7)*4;
                cp16(ao + (r*36 + c)*4, Ag + (size_t)r*HSZ + kc0 + c);
            }
            #pragma unroll
            for (int i = 0; i < 8; i++) {
                int idx = tid + i*256, r = idx >> 3, c = (idx & 7)*4;
                cp16(bo_s + (r*36 + c)*4, Bg + (size_t)r*HSZ + kc0 + c);
            }
            CP_COMMIT();
            CP_WAIT(1);
        } else {
            CP_WAIT(0);
        }
        __syncthreads();

        int buf = ch & 1;
        const uint32_t* A0 = As + buf*128*36 + (warpM*64 + g)*36;
        const uint32_t* B0 = Bs + buf*256*36 + (warpN*64 + g)*36;

        #pragma unroll
        for (int ks = 0; ks < 4; ks++) {
            uint32_t a[4][4], b[8][2];
            #pragma unroll
            for (int mf = 0; mf < 4; mf++) {
                const uint32_t* ap = A0 + mf*16*36 + ks*8 + t4;
                a[mf][0] = ap[0]; a[mf][1] = ap[8*36]; a[mf][2] = ap[4]; a[mf][3] = ap[8*36+4];
            }
            #pragma unroll
            for (int nf = 0; nf < 8; nf++) {
                const uint32_t* bp = B0 + nf*8*36 + ks*8 + t4;
                b[nf][0] = bp[0]; b[nf][1] = bp[4];
            }
            #pragma unroll
            for (int mf = 0; mf < 4; mf++)
                #pragma unroll
                for (int nf = 0; nf < 8; nf++)
                    mma_tf32(acc[mf][nf], a[mf], b[nf]);
        }
        __syncthreads();
    }

    #pragma unroll
    for (int nf = 0; nf < 8; nf++) {
        int v = vb + warpN*64 + nf*8 + t4*2;
        float b0v = bo[v], b1v = bo[v+1];
        #pragma unroll
        for (int mf = 0; mf < 4; mf++) {
            int m_lo = mb + warpM*64 + mf*16 + g;
            int m_hi = m_lo + 8;
            if (m_lo < (TSZ-1)*BSZ) {
                out[(size_t)(m_lo + BSZ)*VSZ + v    ] = acc[mf][nf][0] + b0v;
                out[(size_t)(m_lo + BSZ)*VSZ + v + 1] = acc[mf][nf][1] + b1v;
            }
            if (m_hi < (TSZ-1)*BSZ) {
                out[(size_t)(m_hi + BSZ)*VSZ + v    ] = acc[mf][nf][2] + b0v;
                out[(size_t)(m_hi + BSZ)*VSZ + v + 1] = acc[mf][nf][3] + b1v;
            }
        }
    }
}

// ---------------- host ----------------
extern "C" void kernel_launch(void* const* d_in, const int* in_sizes, int n_in,
                              void* d_out, int out_size) {
    const int*   src_tokens = (const int*)  d_in[0];
    const int*   tgt_tokens = (const int*)  d_in[1];
    const float* enc_emb    = (const float*)d_in[2];
    const float* enc_Wih0   = (const float*)d_in[3];
    const float* enc_Whh0   = (const float*)d_in[4];
    const float* enc_bih0   = (const float*)d_in[5];
    const float* enc_bhh0   = (const float*)d_in[6];
    const float* enc_Wih1   = (const float*)d_in[7];
    const float* enc_Whh1   = (const float*)d_in[8];
    const float* enc_bih1   = (const float*)d_in[9];
    const float* enc_bhh1   = (const float*)d_in[10];
    const float* dec_emb    = (const float*)d_in[11];
    const float* dec_Wih0   = (const float*)d_in[12];
    const float* dec_Whh0   = (const float*)d_in[13];
    const float* dec_bih0   = (const float*)d_in[14];
    const float* dec_bhh0   = (const float*)d_in[15];
    const float* dec_Wih1   = (const float*)d_in[16];
    const float* dec_Whh1   = (const float*)d_in[17];
    const float* dec_bih1   = (const float*)d_in[18];
    const float* dec_bhh1   = (const float*)d_in[19];
    const float* Wc         = (const float*)d_in[20];
    const float* bc         = (const float*)d_in[21];
    const float* Wo         = (const float*)d_in[22];
    const float* bo         = (const float*)d_in[23];
    float* out = (float*)d_out;

    float *emb_src, *emb_dec, *gx_enc, *gx_dec, *enc_out_t;
    float *h1_all, *ctx_all, *cc_all, *wo_tf, *wc_tf;
    cudaGetSymbolAddress((void**)&emb_src,   g_emb_src);
    cudaGetSymbolAddress((void**)&emb_dec,   g_emb_dec);
    cudaGetSymbolAddress((void**)&gx_enc,    g_gx_enc);
    cudaGetSymbolAddress((void**)&gx_dec,    g_gx_dec);
    cudaGetSymbolAddress((void**)&enc_out_t, g_enc_out_t);
    cudaGetSymbolAddress((void**)&h1_all,    g_h1_all);
    cudaGetSymbolAddress((void**)&ctx_all,   g_ctx_all);
    cudaGetSymbolAddress((void**)&cc_all,    g_cc_all);
    cudaGetSymbolAddress((void**)&wo_tf,     g_wo_tf);
    cudaGetSymbolAddress((void**)&wc_tf,     g_wc_tf);

    cudaFuncSetAttribute(rnn_persistent, cudaFuncAttributeMaxDynamicSharedMemorySize, RNN_SMEM);
    cudaFuncSetAttribute(proj_mma,      cudaFuncAttributeMaxDynamicSharedMemorySize, PJ_SMEM);
    cudaFuncSetAttribute(cc_mma,        cudaFuncAttributeMaxDynamicSharedMemorySize, CC_SMEM);
    cudaFuncSetAttribute(logits_mma,    cudaFuncAttributeMaxDynamicSharedMemorySize, LG_SMEM);

    // prep (rnn_persistent = launch #6 for ncu)
    embed_kernel<<<(SSZ*BSZ*ESZ)/256, 256>>>(src_tokens, enc_emb, emb_src, SSZ*BSZ);            // 1
    embed_kernel<<<((TSZ-1)*BSZ*ESZ+255)/256, 256>>>(tgt_tokens, dec_emb, emb_dec, (TSZ-1)*BSZ); // 2
    cvt2_wih0<<<(2*(3*HSZ*ESZ/4))/256, 256>>>(enc_Wih0, dec_Wih0);                              // 3
    proj_mma<<<dim3(16, 24, 2), 256, PJ_SMEM>>>(emb_src, emb_dec, enc_bih0, dec_bih0,
                                                gx_enc, gx_dec, SSZ*BSZ, (TSZ-1)*BSZ);          // 4
    split_all<<<(6*(WSZ/4))/256, 256>>>(enc_Whh0, enc_Wih1, enc_Whh1,
                                        dec_Whh0, dec_Wih1, dec_Whh1);                          // 5

    // whole recurrence: ONE launch (3xtf32, K-chunk 64)                                         // 6
    rnn_persistent<<<NBLK, 256, RNN_SMEM>>>(enc_bhh0, enc_bih1, enc_bhh1,
                                            dec_bhh0, dec_bih1, dec_bhh1);

    // epilogue
    zero_kernel<<<1024, 256>>>(out, BSZ*VSZ);
    cvt_tf32_kernel<<<(VSZ*HSZ/4)/256, 256>>>(Wo, wo_tf);
    cvt_tf32_kernel<<<(HSZ*2*HSZ/4)/256, 256>>>(Wc, wc_tf);
    attn_batched<<<dim3(BSZ, TSZ-1), 256>>>(h1_all, enc_out_t, src_tokens, ctx_all);
    cc_mma<<<dim3(16, 8), 256, CC_SMEM>>>(h1_all, ctx_all, wc_tf, bc, cc_all);
    logits_mma<<<dim3(16, 125), 256, LG_SMEM>>>(cc_all, wo_tf, bo, out);
}

// round 16
// speedup vs baseline: 1.6215x; 1.1048x over previous
#include <cuda_runtime.h>
#include <math.h>
#include <stdint.h>

#define VSZ 32000
#define ESZ 512
#define HSZ 1024
#define SSZ 64
#define TSZ 64
#define BSZ 32
#define BH  (BSZ*HSZ)          // 32768
#define GXS (3*HSZ*BSZ)
#define WSZ (3*HSZ*HSZ)
#define PAD_IDX 1
#define NEGV -100000.0f
#define NBLK 128
#define NPH  128               // fused phases: l1(ph-1) + l0(ph)

// fused-phase smem layout (floats), K-chunk 64
#define TW2 68
#define F_AHI 0                // 96 rows: [Whh0 | Wih1 | Whh1] hi
#define F_ALO (96*TW2)         // 96 rows lo
#define F_XHI (192*TW2)        // 64 rows: [h0cur | h1prev] hi
#define F_XLO (256*TW2)        // 64 rows lo
#define FBUF  (320*TW2)        // 21760 floats
#define RNN_SMEM (2*FBUF*4)    // 174080 B

// ---------------- device scratch ----------------
__device__ float g_emb_src[SSZ*BSZ*ESZ];        // tf32-rounded
__device__ float g_emb_dec[TSZ*BSZ*ESZ];
__device__ float g_wih0_tf[2*3*HSZ*ESZ];
__device__ float g_gx_enc[SSZ*GXS];
__device__ float g_gx_dec[TSZ*GXS];
__device__ float g_enc_out_t[SSZ*BH];
// unified ping-pong hidden states [parity][b][h]
__device__ float g_h0_32[2*BH], g_h0_hi[2*BH], g_h0_lo[2*BH];
__device__ float g_h1_32[2*BH], g_h1_hi[2*BH], g_h1_lo[2*BH];
__device__ float g_h1_all[TSZ*BH];
__device__ float g_ctx_all[TSZ*BH];
__device__ float g_cc_all[TSZ*BH];
__device__ float g_wo_tf[VSZ*HSZ];
__device__ float g_wc_tf[HSZ*2*HSZ];
__device__ float g_whi[6*WSZ];
__device__ float g_wlo[6*WSZ];
__device__ int           g_bar_cnt;
__device__ volatile int  g_bar_sense;

// ---------------- helpers ----------------
__device__ __forceinline__ uint32_t f2tf32(float f) {
    uint32_t u;
    asm("cvt.rna.tf32.f32 %0, %1;" : "=r"(u) : "f"(f));
    return u;
}
__device__ __forceinline__ float tf32v(float f) { return __uint_as_float(f2tf32(f)); }
__device__ __forceinline__ void cp16(uint32_t s, const void* g) {
    asm volatile("cp.async.cg.shared.global [%0], [%1], 16;" :: "r"(s), "l"(g));
}
#define CP_COMMIT() asm volatile("cp.async.commit_group;" ::: "memory")
#define CP_WAIT(N)  asm volatile("cp.async.wait_group %0;" :: "n"(N) : "memory")

__device__ __forceinline__ void mma_tf32(float* c, const uint32_t* a, const uint32_t* b) {
    asm volatile(
        "mma.sync.aligned.m16n8k8.row.col.f32.tf32.tf32.f32 "
        "{%0,%1,%2,%3},{%4,%5,%6,%7},{%8,%9},{%0,%1,%2,%3};"
        : "+f"(c[0]), "+f"(c[1]), "+f"(c[2]), "+f"(c[3])
        : "r"(a[0]), "r"(a[1]), "r"(a[2]), "r"(a[3]), "r"(b[0]), "r"(b[1]));
}

// replay-safe global barrier
__device__ __forceinline__ void gbar(int* sense) {
    __syncthreads();
    if (threadIdx.x == 0) {
        __threadfence();
        int s = (*sense ^= 1);
        if (atomicAdd(&g_bar_cnt, 1) == NBLK - 1) {
            atomicExch(&g_bar_cnt, 0);
            __threadfence();
            g_bar_sense = s;
        } else {
            while (g_bar_sense != s) __nanosleep(32);
        }
    }
    __syncthreads();
}

// ---------------- utility kernels ----------------
__global__ void zero_kernel(float* p, int n) {
    for (int i = blockIdx.x*blockDim.x + threadIdx.x; i < n; i += gridDim.x*blockDim.x)
        p[i] = 0.f;
}
__global__ void cvt_tf32_kernel(const float* __restrict__ in, float* __restrict__ out) {
    int i = blockIdx.x*256 + threadIdx.x;
    float4 v = ((const float4*)in)[i];
    uint4 u = make_uint4(f2tf32(v.x), f2tf32(v.y), f2tf32(v.z), f2tf32(v.w));
    ((uint4*)out)[i] = u;
}
__global__ void cvt2_wih0(const float* __restrict__ a, const float* __restrict__ b) {
    const int N4 = (3*HSZ*ESZ)/4;
    int i = blockIdx.x*256 + threadIdx.x;
    const float* src = (i < N4) ? a : b;
    int k = (i < N4) ? i : i - N4;
    float4 v = ((const float4*)src)[k];
    uint4 u = make_uint4(f2tf32(v.x), f2tf32(v.y), f2tf32(v.z), f2tf32(v.w));
    ((uint4*)g_wih0_tf)[i] = u;
}
__global__ void embed_kernel(const int* __restrict__ tok,
                             const float* __restrict__ emb,
                             float* __restrict__ out, int rows) {
    int idx = blockIdx.x*256 + threadIdx.x;
    if (idx >= rows*ESZ) return;
    int e = idx & (ESZ-1);
    int m = idx >> 9;
    out[idx] = tf32v(emb[(size_t)tok[m]*ESZ + e]);
}
__global__ void split_all(const float* w0, const float* w1, const float* w2,
                          const float* w3, const float* w4, const float* w5) {
    const int N4 = WSZ/4;
    int idx = blockIdx.x*256 + threadIdx.x;
    int m = idx / N4, i = idx - m*N4;
    const float* w = m==0?w0: m==1?w1: m==2?w2: m==3?w3: m==4?w4: w5;
    float4 v = ((const float4*)w)[i];
    float4 hi, lo;
    hi.x = tf32v(v.x); lo.x = tf32v(v.x - hi.x);
    hi.y = tf32v(v.y); lo.y = tf32v(v.y - hi.y);
    hi.z = tf32v(v.z); lo.z = tf32v(v.z - hi.z);
    hi.w = tf32v(v.w); lo.w = tf32v(v.w - hi.w);
    ((float4*)(g_whi + (size_t)m*WSZ))[i] = hi;
    ((float4*)(g_wlo + (size_t)m*WSZ))[i] = lo;
}

// ---------------- input projection via tf32 mma ----------------
#define PJ_SMEM ((2*128*36 + 2*128*36)*4)
__global__ __launch_bounds__(256) void proj_mma(
    const float* __restrict__ Ae, const float* __restrict__ Ad,
    const float* __restrict__ biasE, const float* __restrict__ biasD,
    float* __restrict__ gxE, float* __restrict__ gxD,
    int rowsE, int rowsD)
{
    extern __shared__ uint32_t sm[];
    uint32_t* As = sm;
    uint32_t* Bs = sm + 2*128*36;

    int z = blockIdx.z;
    const float* Am  = z ? Ad : Ae;
    const float* Wt  = g_wih0_tf + (size_t)z*3*HSZ*ESZ;
    const float* bias = z ? biasD : biasE;
    float* gx = z ? gxD : gxE;
    int rows = z ? rowsD : rowsE;

    int tid = threadIdx.x, w = tid >> 5, lane = tid & 31;
    int g = lane >> 2, t4 = lane & 3;
    int warpM = w & 1, warpN = w >> 1;
    int mb = blockIdx.x * 128, nb = blockIdx.y * 128;

    uint32_t as_s = (uint32_t)__cvta_generic_to_shared(As);
    uint32_t bs_s = (uint32_t)__cvta_generic_to_shared(Bs);

    float acc[4][4][4];
    #pragma unroll
    for (int i = 0; i < 4; i++)
        #pragma unroll
        for (int jj = 0; jj < 4; jj++)
            #pragma unroll
            for (int k = 0; k < 4; k++) acc[i][jj][k] = 0.f;

    auto issue = [&](int ch) {
        int kc0 = ch*32, buf = ch & 1;
        uint32_t ao = as_s + buf*128*36*4;
        uint32_t bo2 = bs_s + buf*128*36*4;
        #pragma unroll
        for (int i = 0; i < 4; i++) {
            int idx = tid + i*256, r = idx >> 3, c = (idx & 7)*4;
            cp16(ao + (r*36 + c)*4, Am + (size_t)(mb+r)*ESZ + kc0 + c);
        }
        #pragma unroll
        for (int i = 0; i < 4; i++) {
            int idx = tid + i*256, r = idx >> 3, c = (idx & 7)*4;
            cp16(bo2 + (r*36 + c)*4, Wt + (size_t)(nb+r)*ESZ + kc0 + c);
        }
        CP_COMMIT();
    };

    issue(0);
    for (int ch = 0; ch < 16; ch++) {
        if (ch < 15) { issue(ch+1); CP_WAIT(1); } else { CP_WAIT(0); }
        __syncthreads();
        int buf = ch & 1;
        const uint32_t* A0 = As + buf*128*36 + (warpM*64 + g)*36;
        const uint32_t* B0 = Bs + buf*128*36 + (warpN*32 + g)*36;
        #pragma unroll
        for (int ks = 0; ks < 4; ks++) {
            uint32_t a[4][4], b[4][2];
            #pragma unroll
            for (int mf = 0; mf < 4; mf++) {
                const uint32_t* ap = A0 + mf*16*36 + ks*8 + t4;
                a[mf][0] = ap[0]; a[mf][1] = ap[8*36]; a[mf][2] = ap[4]; a[mf][3] = ap[8*36+4];
            }
            #pragma unroll
            for (int nf = 0; nf < 4; nf++) {
                const uint32_t* bp = B0 + nf*8*36 + ks*8 + t4;
                b[nf][0] = bp[0]; b[nf][1] = bp[4];
            }
            #pragma unroll
            for (int mf = 0; mf < 4; mf++)
                #pragma unroll
                for (int nf = 0; nf < 4; nf++)
                    mma_tf32(acc[mf][nf], a[mf], b[nf]);
        }
        __syncthreads();
    }

    #pragma unroll
    for (int nf = 0; nf < 4; nf++) {
        int n = nb + warpN*32 + nf*8 + t4*2;
        float b0v = bias[n], b1v = bias[n+1];
        #pragma unroll
        for (int mf = 0; mf < 4; mf++) {
            int m_lo = mb + warpM*64 + mf*16 + g;
            int m_hi = m_lo + 8;
            if (m_lo < rows) {
                int t = m_lo >> 5, b = m_lo & 31;
                gx[(size_t)t*GXS + (size_t)n*BSZ + b]     = acc[mf][nf][0] + b0v;
                gx[(size_t)t*GXS + (size_t)(n+1)*BSZ + b] = acc[mf][nf][1] + b1v;
            }
            if (m_hi < rows) {
                int t = m_hi >> 5, b = m_hi & 31;
                gx[(size_t)t*GXS + (size_t)n*BSZ + b]     = acc[mf][nf][2] + b0v;
                gx[(size_t)t*GXS + (size_t)(n+1)*BSZ + b] = acc[mf][nf][3] + b1v;
            }
        }
    }
}

// ---------------- persistent RNN: fused phases ----------------
// Phase ph (0..127): concurrently compute
//   group0: l0 gemm for step ph      (Whh0 · h0cur)     [skipped output at ph==127 is harmless]
//   group1: l1 ih gemm for step ph-1 (Wih1 · h0cur)
//   group2: l1 hh gemm for step ph-1 (Whh1 · h1prev)
// then combine: write h0[wp] (always), h1[wp]+dest (ph>=1).
__global__ __launch_bounds__(256) void rnn_persistent(
    const float* ebhh0, const float* ebih1, const float* ebhh1,
    const float* dbhh0, const float* dbih1, const float* dbhh1)
{
    extern __shared__ float S[];
    uint32_t s_base = (uint32_t)__cvta_generic_to_shared(S);
    int tid = threadIdx.x, w = tid>>5, lane = tid&31;
    int mt = (w>>2)&1, nt = w&3, g = lane>>2, t4 = lane&3;
    int j0 = blockIdx.x*8;
    int sense = g_bar_sense;

    // zero initial hidden: h0 parity 0 (read at phase 0), h1 parity 1 (read at phase 1)
    {
        int jj = tid>>5, b = tid&31;
        size_t o = (size_t)b*HSZ + j0 + jj;
        g_h0_32[o]=0.f; g_h0_hi[o]=0.f; g_h0_lo[o]=0.f;
        g_h1_32[BH+o]=0.f; g_h1_hi[BH+o]=0.f; g_h1_lo[BH+o]=0.f;
    }
    gbar(&sense);

    for (int ph = 0; ph < NPH; ph++) {
        int rp = ph & 1, wp = rp ^ 1;
        bool decL0 = (ph >= 64), decL1 = (ph >= 65);
        const float* A0hi  = g_whi + (decL0 ? 3 : 0)*(size_t)WSZ;
        const float* A0lo  = g_wlo + (decL0 ? 3 : 0)*(size_t)WSZ;
        const float* A1ihi = g_whi + (decL1 ? 4 : 1)*(size_t)WSZ;
        const float* A1ilo = g_wlo + (decL1 ? 4 : 1)*(size_t)WSZ;
        const float* A1hhi = g_whi + (decL1 ? 5 : 2)*(size_t)WSZ;
        const float* A1hlo = g_wlo + (decL1 ? 5 : 2)*(size_t)WSZ;
        const float* gx   = decL0 ? g_gx_dec + (size_t)(ph-64)*GXS
                                  : g_gx_enc + (size_t)ph*GXS;
        const float* bhh0 = decL0 ? dbhh0 : ebhh0;
        const float* bih1 = decL1 ? dbih1 : ebih1;
        const float* bhh1 = decL1 ? dbhh1 : ebhh1;
        const float* h0c_hi = g_h0_hi + rp*BH;
        const float* h0c_lo = g_h0_lo + rp*BH;
        const float* h0c_32 = g_h0_32 + rp*BH;
        const float* h1p_hi = g_h1_hi + rp*BH;
        const float* h1p_lo = g_h1_lo + rp*BH;
        const float* h1p_32 = g_h1_32 + rp*BH;

        float acc[3][4];
        #pragma unroll
        for (int i = 0; i < 3; i++)
            #pragma unroll
            for (int k = 0; k < 4; k++) acc[i][k] = 0.f;

        auto issue = [&](int ch) {
            int kc0 = ch*64, buf = ch&1;
            uint32_t base = s_base + buf*FBUF*4;
            #pragma unroll
            for (int i = 0; i < 20; i++) {
                int idx = tid + i*256;
                int row = idx >> 4, c = (idx & 15)*4;
                const float* src;
                if (row < 192) {
                    int hl = (row >= 96);
                    int ar = hl ? row - 96 : row;     // 0..95
                    int m = ar >> 5;                   // 0,1,2
                    int rl = ar & 31;
                    int gate = rl >> 3, jj2 = rl & 7;
                    size_t grow = (size_t)((gate < 3 ? gate*HSZ : 0) + j0 + jj2);
                    const float* A = hl ? (m==0 ? A0lo : (m==1 ? A1ilo : A1hlo))
                                        : (m==0 ? A0hi : (m==1 ? A1ihi : A1hhi));
                    src = A + grow*HSZ + kc0 + c;
                } else {
                    int hl = (row >= 256);
                    int xr = hl ? row - 256 : row - 192;  // 0..63
                    const float* X = hl ? (xr < 32 ? h0c_lo : h1p_lo)
                                        : (xr < 32 ? h0c_hi : h1p_hi);
                    src = X + (size_t)(xr & 31)*HSZ + kc0 + c;
                }
                cp16(base + (row*TW2 + c)*4, src);
            }
            CP_COMMIT();
        };

        issue(0);
        for (int ch = 0; ch < 16; ch++) {
            if (ch < 15) { issue(ch+1); CP_WAIT(1); } else { CP_WAIT(0); }
            __syncthreads();
            const uint32_t* B = (const uint32_t*)S + (ch&1)*FBUF;
            #pragma unroll
            for (int g3 = 0; g3 < 3; g3++) {
                int arow = g3*32 + mt*16 + g;
                int xrow = (g3 == 2 ? 32 : 0) + nt*8 + g;
                #pragma unroll
                for (int ks = 0; ks < 8; ks++) {
                    const uint32_t* ah = B + F_AHI + arow*TW2 + ks*8 + t4;
                    const uint32_t* al = B + F_ALO + arow*TW2 + ks*8 + t4;
                    const uint32_t* bh = B + F_XHI + xrow*TW2 + ks*8 + t4;
                    const uint32_t* bl = B + F_XLO + xrow*TW2 + ks*8 + t4;
                    uint32_t a0[4] = {ah[0], ah[8*TW2], ah[4], ah[8*TW2+4]};
                    uint32_t a1[4] = {al[0], al[8*TW2], al[4], al[8*TW2+4]};
                    uint32_t b0[2] = {bh[0], bh[4]};
                    uint32_t b1[2] = {bl[0], bl[4]};
                    mma_tf32(acc[g3], a0, b0);
                    mma_tf32(acc[g3], a0, b1);
                    mma_tf32(acc[g3], a1, b0);
                }
            }
            __syncthreads();
        }

        // exchange C tiles: rows g3*32 + [0..23]
        float* Cs = S;
        #pragma unroll
        for (int g3 = 0; g3 < 3; g3++) {
            int r0 = g3*32 + mt*16 + g, c0 = nt*8 + t4*2;
            Cs[r0*33 + c0] = acc[g3][0]; Cs[r0*33 + c0 + 1] = acc[g3][1];
            if (mt == 0) { Cs[(r0+8)*33 + c0] = acc[g3][2]; Cs[(r0+8)*33 + c0 + 1] = acc[g3][3]; }
        }
        __syncthreads();

        int jj = tid>>5, b = tid&31, j = j0 + jj;
        size_t o = (size_t)b*HSZ + j;

        // ---- l0 combine (step ph) ----
        {
            float ghr = Cs[jj*33 + b]      + bhh0[j];
            float ghz = Cs[(8+jj)*33 + b]  + bhh0[HSZ+j];
            float ghn = Cs[(16+jj)*33 + b] + bhh0[2*HSZ+j];
            float gr = gx[(size_t)j*BSZ + b]         + ghr;
            float gz = gx[(size_t)(HSZ+j)*BSZ + b]   + ghz;
            float rr = 1.f/(1.f + expf(-gr));
            float zz = 1.f/(1.f + expf(-gz));
            float nn = tanhf(gx[(size_t)(2*HSZ+j)*BSZ + b] + rr*ghn);
            float hp = __ldcg(h0c_32 + (size_t)b*HSZ + j);
            float h = (1.f - zz)*nn + zz*hp;
            g_h0_32[wp*BH + o] = h;
            float hi = tf32v(h);
            g_h0_hi[wp*BH + o] = hi;
            g_h0_lo[wp*BH + o] = tf32v(h - hi);
        }

        // ---- l1 combine (step ph-1) ----
        if (ph >= 1) {
            float xr = Cs[(32+jj)*33 + b]   + bih1[j];
            float xz = Cs[(40+jj)*33 + b]   + bih1[HSZ+j];
            float xn = Cs[(48+jj)*33 + b]   + bih1[2*HSZ+j];
            float hr = Cs[(64+jj)*33 + b]   + bhh1[j];
            float hz = Cs[(72+jj)*33 + b]   + bhh1[HSZ+j];
            float hn = Cs[(80+jj)*33 + b]   + bhh1[2*HSZ+j];
            float rr = 1.f/(1.f + expf(-(xr + hr)));
            float zz = 1.f/(1.f + expf(-(xz + hz)));
            float nn = tanhf(xn + rr*hn);
            float hp = __ldcg(h1p_32 + (size_t)b*HSZ + j);
            float h = (1.f - zz)*nn + zz*hp;
            g_h1_32[wp*BH + o] = h;
            float hi = tf32v(h);
            g_h1_hi[wp*BH + o] = hi;
            g_h1_lo[wp*BH + o] = tf32v(h - hi);
            int step = ph - 1;
            if (step < SSZ) g_enc_out_t[(size_t)step*BH + o] = h;
            else            g_h1_all[(size_t)(step - SSZ)*BH + o] = hi;
        }
        gbar(&sense);
    }
}

// ---------------- batched attention ----------------
__global__ __launch_bounds__(256) void attn_batched(
    const float* __restrict__ h1_all,
    const float* __restrict__ enc_out_t,
    const int*   __restrict__ src_tokens,
    float* __restrict__ ctx_all)
{
    int b = blockIdx.x, t = blockIdx.y;
    const float* h1t = h1_all + (size_t)t*BH;
    float* ctx = ctx_all + (size_t)t*BH;
    int w = threadIdx.x >> 5, lane = threadIdx.x & 31;
    __shared__ float sc[64];

    float4 q[8];
    #pragma unroll
    for (int c = 0; c < 8; c++)
        q[c] = *(const float4*)(h1t + (size_t)b*HSZ + c*128 + lane*4);

    #pragma unroll
    for (int i = 0; i < 8; i++) {
        int s = w*8 + i;
        const float* e = enc_out_t + ((size_t)s*BSZ + b)*HSZ;
        float acc = 0.f;
        #pragma unroll
        for (int c = 0; c < 8; c++) {
            float4 ev = *(const float4*)(e + c*128 + lane*4);
            acc += q[c].x*ev.x + q[c].y*ev.y + q[c].z*ev.z + q[c].w*ev.w;
        }
        #pragma unroll
        for (int off = 16; off; off >>= 1)
            acc += __shfl_xor_sync(0xffffffffu, acc, off);
        if (lane == 0)
            sc[s] = (src_tokens[s*BSZ + b] != PAD_IDX) ? acc : NEGV;
    }
    __syncthreads();

    if (w == 0) {
        float v0 = sc[lane], v1 = sc[lane+32];
        float m = fmaxf(v0, v1);
        #pragma unroll
        for (int off = 16; off; off >>= 1)
            m = fmaxf(m, __shfl_xor_sync(0xffffffffu, m, off));
        float e0 = expf(v0 - m), e1 = expf(v1 - m);
        float ssum = e0 + e1;
        #pragma unroll
        for (int off = 16; off; off >>= 1)
            ssum += __shfl_xor_sync(0xffffffffu, ssum, off);
        sc[lane]    = e0/ssum;
        sc[lane+32] = e1/ssum;
    }
    __syncthreads();

    float4 a4 = make_float4(0.f, 0.f, 0.f, 0.f);
    for (int s = 0; s < SSZ; s++) {
        float at = sc[s];
        float4 ev = *(const float4*)(enc_out_t + ((size_t)s*BSZ + b)*HSZ + threadIdx.x*4);
        a4.x += at*ev.x; a4.y += at*ev.y; a4.z += at*ev.z; a4.w += at*ev.w;
    }
    uint4 u = make_uint4(f2tf32(a4.x), f2tf32(a4.y), f2tf32(a4.z), f2tf32(a4.w));
    *(uint4*)(ctx + (size_t)b*HSZ + threadIdx.x*4) = u;
}

// ---------------- batched cc GEMM (tf32 mma) ----------------
#define CC_SMEM ((2*128*36 + 2*128*36)*4)
__global__ __launch_bounds__(256) void cc_mma(
    const float* __restrict__ h1a, const float* __restrict__ ctxa,
    const float* __restrict__ wc,  const float* __restrict__ bc,
    float* __restrict__ cc)
{
    extern __shared__ uint32_t sm[];
    uint32_t* As = sm;
    uint32_t* Bs = sm + 2*128*36;

    int tid = threadIdx.x, w = tid >> 5, lane = tid & 31;
    int g = lane >> 2, t4 = lane & 3;
    int warpM = w & 1, warpN = w >> 1;
    int mb = blockIdx.x * 128, nb = blockIdx.y * 128;

    uint32_t as_s = (uint32_t)__cvta_generic_to_shared(As);
    uint32_t bs_s = (uint32_t)__cvta_generic_to_shared(Bs);

    float acc[4][4][4];
    #pragma unroll
    for (int i = 0; i < 4; i++)
        #pragma unroll
        for (int jj = 0; jj < 4; jj++)
            #pragma unroll
            for (int k = 0; k < 4; k++) acc[i][jj][k] = 0.f;

    auto issue = [&](int ch) {
        int kc0 = ch*32, buf = ch & 1;
        uint32_t ao = as_s + buf*128*36*4;
        uint32_t bo2 = bs_s + buf*128*36*4;
        #pragma unroll
        for (int i = 0; i < 4; i++) {
            int idx = tid + i*256, r = idx >> 3, c = (idx & 7)*4;
            int k = kc0 + c;
            const float* src = (k < HSZ) ? (h1a + (size_t)(mb+r)*HSZ + k)
                                         : (ctxa + (size_t)(mb+r)*HSZ + (k - HSZ));
            cp16(ao + (r*36 + c)*4, src);
        }
        #pragma unroll
        for (int i = 0; i < 4; i++) {
            int idx = tid + i*256, r = idx >> 3, c = (idx & 7)*4;
            cp16(bo2 + (r*36 + c)*4, wc + (size_t)(nb+r)*(2*HSZ) + kc0 + c);
        }
        CP_COMMIT();
    };

    issue(0);
    for (int ch = 0; ch < 64; ch++) {
        if (ch < 63) { issue(ch+1); CP_WAIT(1); } else { CP_WAIT(0); }
        __syncthreads();
        int buf = ch & 1;
        const uint32_t* A0 = As + buf*128*36 + (warpM*64 + g)*36;
        const uint32_t* B0 = Bs + buf*128*36 + (warpN*32 + g)*36;
        #pragma unroll
        for (int ks = 0; ks < 4; ks++) {
            uint32_t a[4][4], b[4][2];
            #pragma unroll
            for (int mf = 0; mf < 4; mf++) {
                const uint32_t* ap = A0 + mf*16*36 + ks*8 + t4;
                a[mf][0] = ap[0]; a[mf][1] = ap[8*36]; a[mf][2] = ap[4]; a[mf][3] = ap[8*36+4];
            }
            #pragma unroll
            for (int nf = 0; nf < 4; nf++) {
                const uint32_t* bp = B0 + nf*8*36 + ks*8 + t4;
                b[nf][0] = bp[0]; b[nf][1] = bp[4];
            }
            #pragma unroll
            for (int mf = 0; mf < 4; mf++)
                #pragma unroll
                for (int nf = 0; nf < 4; nf++)
                    mma_tf32(acc[mf][nf], a[mf], b[nf]);
        }
        __syncthreads();
    }

    #pragma unroll
    for (int nf = 0; nf < 4; nf++) {
        int n = nb + warpN*32 + nf*8 + t4*2;
        float b0v = bc[n], b1v = bc[n+1];
        #pragma unroll
        for (int mf = 0; mf < 4; mf++) {
            int m_lo = mb + warpM*64 + mf*16 + g;
            int m_hi = m_lo + 8;
            if (m_lo < (TSZ-1)*BSZ) {
                cc[(size_t)m_lo*HSZ + n  ] = tf32v(tanhf(acc[mf][nf][0] + b0v));
                cc[(size_t)m_lo*HSZ + n+1] = tf32v(tanhf(acc[mf][nf][1] + b1v));
            }
            if (m_hi < (TSZ-1)*BSZ) {
                cc[(size_t)m_hi*HSZ + n  ] = tf32v(tanhf(acc[mf][nf][2] + b0v));
                cc[(size_t)m_hi*HSZ + n+1] = tf32v(tanhf(acc[mf][nf][3] + b1v));
            }
        }
    }
}

// ---------------- logits GEMM (tf32 mma) ----------------
#define LG_SMEM ((2*128*36 + 2*256*36)*4)
__global__ __launch_bounds__(256) void logits_mma(
    const float* __restrict__ cc, const float* __restrict__ wo,
    const float* __restrict__ bo, float* __restrict__ out)
{
    extern __shared__ uint32_t sm[];
    uint32_t* As = sm;
    uint32_t* Bs = sm + 2*128*36;

    int tid = threadIdx.x, w = tid >> 5, lane = tid & 31;
    int g = lane >> 2, t4 = lane & 3;
    int warpM = w & 1, warpN = w >> 1;
    int mb = blockIdx.x * 128, vb = blockIdx.y * 256;

    const float* Ag = cc + (size_t)mb*HSZ;
    const float* Bg = wo + (size_t)vb*HSZ;
    uint32_t as_s = (uint32_t)__cvta_generic_to_shared(As);
    uint32_t bs_s = (uint32_t)__cvta_generic_to_shared(Bs);

    float acc[4][8][4];
    #pragma unroll
    for (int i = 0; i < 4; i++)
        #pragma unroll
        for (int jj = 0; jj < 8; jj++)
            #pragma unroll
            for (int k = 0; k < 4; k++) acc[i][jj][k] = 0.f;

    {
        #pragma unroll
        for (int i = 0; i < 4; i++) {
            int idx = tid + i*256, r = idx >> 3, c = (idx & 7)*4;
            cp16(as_s + (r*36 + c)*4, Ag + (size_t)r*HSZ + c);
        }
        #pragma unroll
        for (int i = 0; i < 8; i++) {
            int idx = tid + i*256, r = idx >> 3, c = (idx & 7)*4;
            cp16(bs_s + (r*36 + c)*4, Bg + (size_t)r*HSZ + c);
        }
        CP_COMMIT();
    }

    for (int ch = 0; ch < 32; ch++) {
        if (ch < 31) {
            int kc0 = (ch+1)*32, buf = (ch+1) & 1;
            uint32_t ao = as_s + buf*128*36*4;
            uint32_t bo_s = bs_s + buf*256*36*4;
            #pragma unroll
            for (int i = 0; i < 4; i++) {
                int idx = tid + i*256, r = idx >> 3, c = (idx & 7)*4;
                cp16(ao + (r*36 + c)*4, Ag + (size_t)r*HSZ + kc0 + c);
            }
            #pragma unroll
            for (int i = 0; i < 8; i++) {
                int idx = tid + i*256, r = idx >> 3, c = (idx & 7)*4;
                cp16(bo_s + (r*36 + c)*4, Bg + (size_t)r*HSZ + kc0 + c);
            }
            CP_COMMIT();
            CP_WAIT(1);
        } else {
            CP_WAIT(0);
        }
        __syncthreads();

        int buf = ch & 1;
        const uint32_t* A0 = As + buf*128*36 + (warpM*64 + g)*36;
        const uint32_t* B0 = Bs + buf*256*36 + (warpN*64 + g)*36;

        #pragma unroll
        for (int ks = 0; ks < 4; ks++) {
            uint32_t a[4][4], b[8][2];
            #pragma unroll
            for (int mf = 0; mf < 4; mf++) {
                const uint32_t* ap = A0 + mf*16*36 + ks*8 + t4;
                a[mf][0] = ap[0]; a[mf][1] = ap[8*36]; a[mf][2] = ap[4]; a[mf][3] = ap[8*36+4];
            }
            #pragma unroll
            for (int nf = 0; nf < 8; nf++) {
                const uint32_t* bp = B0 + nf*8*36 + ks*8 + t4;
                b[nf][0] = bp[0]; b[nf][1] = bp[4];
            }
            #pragma unroll
            for (int mf = 0; mf < 4; mf++)
                #pragma unroll
                for (int nf = 0; nf < 8; nf++)
                    mma_tf32(acc[mf][nf], a[mf], b[nf]);
        }
        __syncthreads();
    }

    #pragma unroll
    for (int nf = 0; nf < 8; nf++) {
        int v = vb + warpN*64 + nf*8 + t4*2;
        float b0v = bo[v], b1v = bo[v+1];
        #pragma unroll
        for (int mf = 0; mf < 4; mf++) {
            int m_lo = mb + warpM*64 + mf*16 + g;
            int m_hi = m_lo + 8;
            if (m_lo < (TSZ-1)*BSZ) {
                out[(size_t)(m_lo + BSZ)*VSZ + v    ] = acc[mf][nf][0] + b0v;
                out[(size_t)(m_lo + BSZ)*VSZ + v + 1] = acc[mf][nf][1] + b1v;
            }
            if (m_hi < (TSZ-1)*BSZ) {
                out[(size_t)(m_hi + BSZ)*VSZ + v    ] = acc[mf][nf][2] + b0v;
                out[(size_t)(m_hi + BSZ)*VSZ + v + 1] = acc[mf][nf][3] + b1v;
            }
        }
    }
}

// ---------------- host ----------------
extern "C" void kernel_launch(void* const* d_in, const int* in_sizes, int n_in,
                              void* d_out, int out_size) {
    const int*   src_tokens = (const int*)  d_in[0];
    const int*   tgt_tokens = (const int*)  d_in[1];
    const float* enc_emb    = (const float*)d_in[2];
    const float* enc_Wih0   = (const float*)d_in[3];
    const float* enc_Whh0   = (const float*)d_in[4];
    const float* enc_bih0   = (const float*)d_in[5];
    const float* enc_bhh0   = (const float*)d_in[6];
    const float* enc_Wih1   = (const float*)d_in[7];
    const float* enc_Whh1   = (const float*)d_in[8];
    const float* enc_bih1   = (const float*)d_in[9];
    const float* enc_bhh1   = (const float*)d_in[10];
    const float* dec_emb    = (const float*)d_in[11];
    const float* dec_Wih0   = (const float*)d_in[12];
    const float* dec_Whh0   = (const float*)d_in[13];
    const float* dec_bih0   = (const float*)d_in[14];
    const float* dec_bhh0   = (const float*)d_in[15];
    const float* dec_Wih1   = (const float*)d_in[16];
    const float* dec_Whh1   = (const float*)d_in[17];
    const float* dec_bih1   = (const float*)d_in[18];
    const float* dec_bhh1   = (const float*)d_in[19];
    const float* Wc         = (const float*)d_in[20];
    const float* bc         = (const float*)d_in[21];
    const float* Wo         = (const float*)d_in[22];
    const float* bo         = (const float*)d_in[23];
    float* out = (float*)d_out;

    float *emb_src, *emb_dec, *gx_enc, *gx_dec, *enc_out_t;
    float *h1_all, *ctx_all, *cc_all, *wo_tf, *wc_tf;
    cudaGetSymbolAddress((void**)&emb_src,   g_emb_src);
    cudaGetSymbolAddress((void**)&emb_dec,   g_emb_dec);
    cudaGetSymbolAddress((void**)&gx_enc,    g_gx_enc);
    cudaGetSymbolAddress((void**)&gx_dec,    g_gx_dec);
    cudaGetSymbolAddress((void**)&enc_out_t, g_enc_out_t);
    cudaGetSymbolAddress((void**)&h1_all,    g_h1_all);
    cudaGetSymbolAddress((void**)&ctx_all,   g_ctx_all);
    cudaGetSymbolAddress((void**)&cc_all,    g_cc_all);
    cudaGetSymbolAddress((void**)&wo_tf,     g_wo_tf);
    cudaGetSymbolAddress((void**)&wc_tf,     g_wc_tf);

    cudaFuncSetAttribute(rnn_persistent, cudaFuncAttributeMaxDynamicSharedMemorySize, RNN_SMEM);
    cudaFuncSetAttribute(proj_mma,      cudaFuncAttributeMaxDynamicSharedMemorySize, PJ_SMEM);
    cudaFuncSetAttribute(cc_mma,        cudaFuncAttributeMaxDynamicSharedMemorySize, CC_SMEM);
    cudaFuncSetAttribute(logits_mma,    cudaFuncAttributeMaxDynamicSharedMemorySize, LG_SMEM);

    // prep (rnn_persistent = launch #6 for ncu)
    embed_kernel<<<(SSZ*BSZ*ESZ)/256, 256>>>(src_tokens, enc_emb, emb_src, SSZ*BSZ);            // 1
    embed_kernel<<<((TSZ-1)*BSZ*ESZ+255)/256, 256>>>(tgt_tokens, dec_emb, emb_dec, (TSZ-1)*BSZ); // 2
    cvt2_wih0<<<(2*(3*HSZ*ESZ/4))/256, 256>>>(enc_Wih0, dec_Wih0);                              // 3
    proj_mma<<<dim3(16, 24, 2), 256, PJ_SMEM>>>(emb_src, emb_dec, enc_bih0, dec_bih0,
                                                gx_enc, gx_dec, SSZ*BSZ, (TSZ-1)*BSZ);          // 4
    split_all<<<(6*(WSZ/4))/256, 256>>>(enc_Whh0, enc_Wih1, enc_Whh1,
                                        dec_Whh0, dec_Wih1, dec_Whh1);                          // 5

    // recurrence: ONE launch, 128 fused phases                                                  // 6
    rnn_persistent<<<NBLK, 256, RNN_SMEM>>>(enc_bhh0, enc_bih1, enc_bhh1,
                                            dec_bhh0, dec_bih1, dec_bhh1);

    // epilogue
    zero_kernel<<<1024, 256>>>(out, BSZ*VSZ);
    cvt_tf32_kernel<<<(VSZ*HSZ/4)/256, 256>>>(Wo, wo_tf);
    cvt_tf32_kernel<<<(HSZ*2*HSZ/4)/256, 256>>>(Wc, wc_tf);
    attn_batched<<<dim3(BSZ, TSZ-1), 256>>>(h1_all, enc_out_t, src_tokens, ctx_all);
    cc_mma<<<dim3(16, 8), 256, CC_SMEM>>>(h1_all, ctx_all, wc_tf, bc, cc_all);
    logits_mma<<<dim3(16, 125), 256, LG_SMEM>>>(cc_all, wo_tf, bo, out);
}

// round 17
// speedup vs baseline: 1.7010x; 1.0490x over previous
#include <cuda_runtime.h>
#include <cuda_bf16.h>
#include <math.h>
#include <stdint.h>

#define VSZ 32000
#define ESZ 512
#define HSZ 1024
#define SSZ 64
#define TSZ 64
#define BSZ 32
#define BH  (BSZ*HSZ)          // 32768
#define GXS (3*HSZ*BSZ)
#define WSZ (3*HSZ*HSZ)
#define PAD_IDX 1
#define NEGV -100000.0f
#define NBLK 128
#define NPH  128
#define NCH  8                 // K chunks of 128 elements

// fused-phase smem layout (32-bit words; 1 word = 2 bf16 = 2 k)
#define TW3 68                 // 64 data words (=128 k) + 4 pad
#define F_AHI 0                // 96 rows: [Whh0 | Wih1 | Whh1] hi
#define F_ALO (96*TW3)         // 96 rows lo
#define F_XHI (192*TW3)        // 64 rows: [h0cur | h1prev] hi
#define F_XLO (256*TW3)        // 64 rows lo
#define FBUF  (320*TW3)        // 21760 words
#define RNN_SMEM (2*FBUF*4)    // 174080 B

// ---------------- device scratch ----------------
__device__ float g_emb_src[SSZ*BSZ*ESZ];        // tf32-rounded
__device__ float g_emb_dec[TSZ*BSZ*ESZ];
__device__ float g_wih0_tf[2*3*HSZ*ESZ];
__device__ float g_gx_enc[SSZ*GXS];
__device__ float g_gx_dec[TSZ*GXS];
__device__ float g_enc_out_t[SSZ*BH];
// hidden states: fp32 (for z*h path + enc_out) and bf16 hi/lo (mma operands)
__device__ float g_h0_32[2*BH];
__device__ float g_h1_32[2*BH];
__device__ __nv_bfloat16 g_h0_bhi[2*BH], g_h0_blo[2*BH];
__device__ __nv_bfloat16 g_h1_bhi[2*BH], g_h1_blo[2*BH];
__device__ float g_h1_all[TSZ*BH];              // tf32-rounded (cc_mma operand)
__device__ float g_ctx_all[TSZ*BH];
__device__ float g_cc_all[TSZ*BH];
__device__ float g_wo_tf[VSZ*HSZ];
__device__ float g_wc_tf[HSZ*2*HSZ];
// recurrent weights, bf16 hi/lo: order eWhh0,eWih1,eWhh1,dWhh0,dWih1,dWhh1
__device__ __nv_bfloat16 g_wbhi[6*WSZ];
__device__ __nv_bfloat16 g_wblo[6*WSZ];
__device__ int           g_bar_cnt;
__device__ volatile int  g_bar_sense;

// ---------------- helpers ----------------
__device__ __forceinline__ uint32_t f2tf32(float f) {
    uint32_t u;
    asm("cvt.rna.tf32.f32 %0, %1;" : "=r"(u) : "f"(f));
    return u;
}
__device__ __forceinline__ float tf32v(float f) { return __uint_as_float(f2tf32(f)); }
__device__ __forceinline__ void cp16(uint32_t s, const void* g) {
    asm volatile("cp.async.cg.shared.global [%0], [%1], 16;" :: "r"(s), "l"(g));
}
#define CP_COMMIT() asm volatile("cp.async.commit_group;" ::: "memory")
#define CP_WAIT(N)  asm volatile("cp.async.wait_group %0;" :: "n"(N) : "memory")

__device__ __forceinline__ void mma_tf32(float* c, const uint32_t* a, const uint32_t* b) {
    asm volatile(
        "mma.sync.aligned.m16n8k8.row.col.f32.tf32.tf32.f32 "
        "{%0,%1,%2,%3},{%4,%5,%6,%7},{%8,%9},{%0,%1,%2,%3};"
        : "+f"(c[0]), "+f"(c[1]), "+f"(c[2]), "+f"(c[3])
        : "r"(a[0]), "r"(a[1]), "r"(a[2]), "r"(a[3]), "r"(b[0]), "r"(b[1]));
}
__device__ __forceinline__ void mma_bf16(float* c, const uint32_t* a, const uint32_t* b) {
    asm volatile(
        "mma.sync.aligned.m16n8k16.row.col.f32.bf16.bf16.f32 "
        "{%0,%1,%2,%3},{%4,%5,%6,%7},{%8,%9},{%0,%1,%2,%3};"
        : "+f"(c[0]), "+f"(c[1]), "+f"(c[2]), "+f"(c[3])
        : "r"(a[0]), "r"(a[1]), "r"(a[2]), "r"(a[3]), "r"(b[0]), "r"(b[1]));
}

// replay-safe global barrier
__device__ __forceinline__ void gbar(int* sense) {
    __syncthreads();
    if (threadIdx.x == 0) {
        __threadfence();
        int s = (*sense ^= 1);
        if (atomicAdd(&g_bar_cnt, 1) == NBLK - 1) {
            atomicExch(&g_bar_cnt, 0);
            __threadfence();
            g_bar_sense = s;
        } else {
            while (g_bar_sense != s) __nanosleep(32);
        }
    }
    __syncthreads();
}

// ---------------- utility kernels ----------------
__global__ void zero_kernel(float* p, int n) {
    for (int i = blockIdx.x*blockDim.x + threadIdx.x; i < n; i += gridDim.x*blockDim.x)
        p[i] = 0.f;
}
__global__ void cvt_tf32_kernel(const float* __restrict__ in, float* __restrict__ out) {
    int i = blockIdx.x*256 + threadIdx.x;
    float4 v = ((const float4*)in)[i];
    uint4 u = make_uint4(f2tf32(v.x), f2tf32(v.y), f2tf32(v.z), f2tf32(v.w));
    ((uint4*)out)[i] = u;
}
__global__ void cvt2_wih0(const float* __restrict__ a, const float* __restrict__ b) {
    const int N4 = (3*HSZ*ESZ)/4;
    int i = blockIdx.x*256 + threadIdx.x;
    const float* src = (i < N4) ? a : b;
    int k = (i < N4) ? i : i - N4;
    float4 v = ((const float4*)src)[k];
    uint4 u = make_uint4(f2tf32(v.x), f2tf32(v.y), f2tf32(v.z), f2tf32(v.w));
    ((uint4*)g_wih0_tf)[i] = u;
}
__global__ void embed_kernel(const int* __restrict__ tok,
                             const float* __restrict__ emb,
                             float* __restrict__ out, int rows) {
    int idx = blockIdx.x*256 + threadIdx.x;
    if (idx >= rows*ESZ) return;
    int e = idx & (ESZ-1);
    int m = idx >> 9;
    out[idx] = tf32v(emb[(size_t)tok[m]*ESZ + e]);
}
// split 6 recurrent weight matrices into bf16 hi/lo
__global__ void split_all(const float* w0, const float* w1, const float* w2,
                          const float* w3, const float* w4, const float* w5) {
    const int N4 = WSZ/4;
    int idx = blockIdx.x*256 + threadIdx.x;
    int m = idx / N4, i = idx - m*N4;
    const float* w = m==0?w0: m==1?w1: m==2?w2: m==3?w3: m==4?w4: w5;
    float4 v = ((const float4*)w)[i];
    __nv_bfloat16 hx = __float2bfloat16(v.x);
    __nv_bfloat16 hy = __float2bfloat16(v.y);
    __nv_bfloat16 hz = __float2bfloat16(v.z);
    __nv_bfloat16 hw = __float2bfloat16(v.w);
    __nv_bfloat16 lx = __float2bfloat16(v.x - __bfloat162float(hx));
    __nv_bfloat16 ly = __float2bfloat16(v.y - __bfloat162float(hy));
    __nv_bfloat16 lz = __float2bfloat16(v.z - __bfloat162float(hz));
    __nv_bfloat16 lw = __float2bfloat16(v.w - __bfloat162float(hw));
    __nv_bfloat162* dh = (__nv_bfloat162*)(g_wbhi + (size_t)m*WSZ);
    __nv_bfloat162* dl = (__nv_bfloat162*)(g_wblo + (size_t)m*WSZ);
    dh[i*2]   = __nv_bfloat162(hx, hy);
    dh[i*2+1] = __nv_bfloat162(hz, hw);
    dl[i*2]   = __nv_bfloat162(lx, ly);
    dl[i*2+1] = __nv_bfloat162(lz, lw);
}

// ---------------- input projection via tf32 mma ----------------
#define PJ_SMEM ((2*128*36 + 2*128*36)*4)
__global__ __launch_bounds__(256) void proj_mma(
    const float* __restrict__ Ae, const float* __restrict__ Ad,
    const float* __restrict__ biasE, const float* __restrict__ biasD,
    float* __restrict__ gxE, float* __restrict__ gxD,
    int rowsE, int rowsD)
{
    extern __shared__ uint32_t sm[];
    uint32_t* As = sm;
    uint32_t* Bs = sm + 2*128*36;

    int z = blockIdx.z;
    const float* Am  = z ? Ad : Ae;
    const float* Wt  = g_wih0_tf + (size_t)z*3*HSZ*ESZ;
    const float* bias = z ? biasD : biasE;
    float* gx = z ? gxD : gxE;
    int rows = z ? rowsD : rowsE;

    int tid = threadIdx.x, w = tid >> 5, lane = tid & 31;
    int g = lane >> 2, t4 = lane & 3;
    int warpM = w & 1, warpN = w >> 1;
    int mb = blockIdx.x * 128, nb = blockIdx.y * 128;

    uint32_t as_s = (uint32_t)__cvta_generic_to_shared(As);
    uint32_t bs_s = (uint32_t)__cvta_generic_to_shared(Bs);

    float acc[4][4][4];
    #pragma unroll
    for (int i = 0; i < 4; i++)
        #pragma unroll
        for (int jj = 0; jj < 4; jj++)
            #pragma unroll
            for (int k = 0; k < 4; k++) acc[i][jj][k] = 0.f;

    auto issue = [&](int ch) {
        int kc0 = ch*32, buf = ch & 1;
        uint32_t ao = as_s + buf*128*36*4;
        uint32_t bo2 = bs_s + buf*128*36*4;
        #pragma unroll
        for (int i = 0; i < 4; i++) {
            int idx = tid + i*256, r = idx >> 3, c = (idx & 7)*4;
            cp16(ao + (r*36 + c)*4, Am + (size_t)(mb+r)*ESZ + kc0 + c);
        }
        #pragma unroll
        for (int i = 0; i < 4; i++) {
            int idx = tid + i*256, r = idx >> 3, c = (idx & 7)*4;
            cp16(bo2 + (r*36 + c)*4, Wt + (size_t)(nb+r)*ESZ + kc0 + c);
        }
        CP_COMMIT();
    };

    issue(0);
    for (int ch = 0; ch < 16; ch++) {
        if (ch < 15) { issue(ch+1); CP_WAIT(1); } else { CP_WAIT(0); }
        __syncthreads();
        int buf = ch & 1;
        const uint32_t* A0 = As + buf*128*36 + (warpM*64 + g)*36;
        const uint32_t* B0 = Bs + buf*128*36 + (warpN*32 + g)*36;
        #pragma unroll
        for (int ks = 0; ks < 4; ks++) {
            uint32_t a[4][4], b[4][2];
            #pragma unroll
            for (int mf = 0; mf < 4; mf++) {
                const uint32_t* ap = A0 + mf*16*36 + ks*8 + t4;
                a[mf][0] = ap[0]; a[mf][1] = ap[8*36]; a[mf][2] = ap[4]; a[mf][3] = ap[8*36+4];
            }
            #pragma unroll
            for (int nf = 0; nf < 4; nf++) {
                const uint32_t* bp = B0 + nf*8*36 + ks*8 + t4;
                b[nf][0] = bp[0]; b[nf][1] = bp[4];
            }
            #pragma unroll
            for (int mf = 0; mf < 4; mf++)
                #pragma unroll
                for (int nf = 0; nf < 4; nf++)
                    mma_tf32(acc[mf][nf], a[mf], b[nf]);
        }
        __syncthreads();
    }

    #pragma unroll
    for (int nf = 0; nf < 4; nf++) {
        int n = nb + warpN*32 + nf*8 + t4*2;
        float b0v = bias[n], b1v = bias[n+1];
        #pragma unroll
        for (int mf = 0; mf < 4; mf++) {
            int m_lo = mb + warpM*64 + mf*16 + g;
            int m_hi = m_lo + 8;
            if (m_lo < rows) {
                int t = m_lo >> 5, b = m_lo & 31;
                gx[(size_t)t*GXS + (size_t)n*BSZ + b]     = acc[mf][nf][0] + b0v;
                gx[(size_t)t*GXS + (size_t)(n+1)*BSZ + b] = acc[mf][nf][1] + b1v;
            }
            if (m_hi < rows) {
                int t = m_hi >> 5, b = m_hi & 31;
                gx[(size_t)t*GXS + (size_t)n*BSZ + b]     = acc[mf][nf][2] + b0v;
                gx[(size_t)t*GXS + (size_t)(n+1)*BSZ + b] = acc[mf][nf][3] + b1v;
            }
        }
    }
}

// ---------------- persistent RNN: fused phases, bf16 hi/lo 3-term ----------
__global__ __launch_bounds__(256) void rnn_persistent(
    const float* ebhh0, const float* ebih1, const float* ebhh1,
    const float* dbhh0, const float* dbih1, const float* dbhh1)
{
    extern __shared__ float S[];
    uint32_t s_base = (uint32_t)__cvta_generic_to_shared(S);
    int tid = threadIdx.x, w = tid>>5, lane = tid&31;
    int mt = (w>>2)&1, nt = w&3, g = lane>>2, t4 = lane&3;
    int j0 = blockIdx.x*8;
    int sense = g_bar_sense;

    // zero initial hidden: h0 parity 0, h1 parity 1
    {
        int jj = tid>>5, b = tid&31;
        size_t o = (size_t)b*HSZ + j0 + jj;
        __nv_bfloat16 zb = __float2bfloat16(0.f);
        g_h0_32[o]=0.f;    g_h0_bhi[o]=zb;    g_h0_blo[o]=zb;
        g_h1_32[BH+o]=0.f; g_h1_bhi[BH+o]=zb; g_h1_blo[BH+o]=zb;
    }
    gbar(&sense);

    for (int ph = 0; ph < NPH; ph++) {
        int rp = ph & 1, wp = rp ^ 1;
        bool decL0 = (ph >= 64), decL1 = (ph >= 65);
        const __nv_bfloat16* A0hi  = g_wbhi + (decL0 ? 3 : 0)*(size_t)WSZ;
        const __nv_bfloat16* A0lo  = g_wblo + (decL0 ? 3 : 0)*(size_t)WSZ;
        const __nv_bfloat16* A1ihi = g_wbhi + (decL1 ? 4 : 1)*(size_t)WSZ;
        const __nv_bfloat16* A1ilo = g_wblo + (decL1 ? 4 : 1)*(size_t)WSZ;
        const __nv_bfloat16* A1hhi = g_wbhi + (decL1 ? 5 : 2)*(size_t)WSZ;
        const __nv_bfloat16* A1hlo = g_wblo + (decL1 ? 5 : 2)*(size_t)WSZ;
        const float* gx   = decL0 ? g_gx_dec + (size_t)(ph-64)*GXS
                                  : g_gx_enc + (size_t)ph*GXS;
        const float* bhh0 = decL0 ? dbhh0 : ebhh0;
        const float* bih1 = decL1 ? dbih1 : ebih1;
        const float* bhh1 = decL1 ? dbhh1 : ebhh1;
        const __nv_bfloat16* h0c_bhi = g_h0_bhi + rp*BH;
        const __nv_bfloat16* h0c_blo = g_h0_blo + rp*BH;
        const __nv_bfloat16* h1p_bhi = g_h1_bhi + rp*BH;
        const __nv_bfloat16* h1p_blo = g_h1_blo + rp*BH;
        const float* h0c_32 = g_h0_32 + rp*BH;
        const float* h1p_32 = g_h1_32 + rp*BH;

        float acc[3][4];
        #pragma unroll
        for (int i = 0; i < 3; i++)
            #pragma unroll
            for (int k = 0; k < 4; k++) acc[i][k] = 0.f;

        auto issue = [&](int ch) {
            int kc0 = ch*128, buf = ch&1;       // element offset in k
            uint32_t base = s_base + buf*FBUF*4;
            #pragma unroll
            for (int i = 0; i < 20; i++) {
                int idx = tid + i*256;
                int row = idx >> 4;
                int ce = (idx & 15)*8;          // element offset within chunk (8 bf16/cp16)
                const __nv_bfloat16* src;
                if (row < 192) {
                    int hl = (row >= 96);
                    int ar = hl ? row - 96 : row;
                    int m = ar >> 5;
                    int rl = ar & 31;
                    int gate = rl >> 3, jj2 = rl & 7;
                    size_t grow = (size_t)((gate < 3 ? gate*HSZ : 0) + j0 + jj2);
                    const __nv_bfloat16* A = hl ? (m==0 ? A0lo : (m==1 ? A1ilo : A1hlo))
                                                : (m==0 ? A0hi : (m==1 ? A1ihi : A1hhi));
                    src = A + grow*HSZ + kc0 + ce;
                } else {
                    int hl = (row >= 256);
                    int xr = hl ? row - 256 : row - 192;
                    const __nv_bfloat16* X = hl ? (xr < 32 ? h0c_blo : h1p_blo)
                                                : (xr < 32 ? h0c_bhi : h1p_bhi);
                    src = X + (size_t)(xr & 31)*HSZ + kc0 + ce;
                }
                // dest word = ce/2 = (idx&15)*4
                cp16(base + (row*TW3 + (idx & 15)*4)*4, src);
            }
            CP_COMMIT();
        };

        issue(0);
        for (int ch = 0; ch < NCH; ch++) {
            if (ch < NCH-1) { issue(ch+1); CP_WAIT(1); } else { CP_WAIT(0); }
            __syncthreads();
            const uint32_t* B = (const uint32_t*)S + (ch&1)*FBUF;
            #pragma unroll
            for (int g3 = 0; g3 < 3; g3++) {
                int arow = g3*32 + mt*16 + g;
                int xrow = (g3 == 2 ? 32 : 0) + nt*8 + g;
                #pragma unroll
                for (int ks = 0; ks < 8; ks++) {
                    const uint32_t* ah = B + F_AHI + arow*TW3 + ks*8 + t4;
                    const uint32_t* al = B + F_ALO + arow*TW3 + ks*8 + t4;
                    const uint32_t* bh = B + F_XHI + xrow*TW3 + ks*8 + t4;
                    const uint32_t* bl = B + F_XLO + xrow*TW3 + ks*8 + t4;
                    uint32_t a0[4] = {ah[0], ah[8*TW3], ah[4], ah[8*TW3+4]};
                    uint32_t a1[4] = {al[0], al[8*TW3], al[4], al[8*TW3+4]};
                    uint32_t b0[2] = {bh[0], bh[4]};
                    uint32_t b1[2] = {bl[0], bl[4]};
                    mma_bf16(acc[g3], a0, b0);
                    mma_bf16(acc[g3], a0, b1);
                    mma_bf16(acc[g3], a1, b0);
                }
            }
            __syncthreads();
        }

        // exchange C tiles
        float* Cs = S;
        #pragma unroll
        for (int g3 = 0; g3 < 3; g3++) {
            int r0 = g3*32 + mt*16 + g, c0 = nt*8 + t4*2;
            Cs[r0*33 + c0] = acc[g3][0]; Cs[r0*33 + c0 + 1] = acc[g3][1];
            if (mt == 0) { Cs[(r0+8)*33 + c0] = acc[g3][2]; Cs[(r0+8)*33 + c0 + 1] = acc[g3][3]; }
        }
        __syncthreads();

        int jj = tid>>5, b = tid&31, j = j0 + jj;
        size_t o = (size_t)b*HSZ + j;

        // ---- l0 combine (step ph) ----
        {
            float ghr = Cs[jj*33 + b]      + bhh0[j];
            float ghz = Cs[(8+jj)*33 + b]  + bhh0[HSZ+j];
            float ghn = Cs[(16+jj)*33 + b] + bhh0[2*HSZ+j];
            float gr = gx[(size_t)j*BSZ + b]         + ghr;
            float gz = gx[(size_t)(HSZ+j)*BSZ + b]   + ghz;
            float rr = 1.f/(1.f + expf(-gr));
            float zz = 1.f/(1.f + expf(-gz));
            float nn = tanhf(gx[(size_t)(2*HSZ+j)*BSZ + b] + rr*ghn);
            float hp = __ldcg(h0c_32 + (size_t)b*HSZ + j);
            float h = (1.f - zz)*nn + zz*hp;
            g_h0_32[wp*BH + o] = h;
            __nv_bfloat16 hb = __float2bfloat16(h);
            g_h0_bhi[wp*BH + o] = hb;
            g_h0_blo[wp*BH + o] = __float2bfloat16(h - __bfloat162float(hb));
        }

        // ---- l1 combine (step ph-1) ----
        if (ph >= 1) {
            float xr = Cs[(32+jj)*33 + b]   + bih1[j];
            float xz = Cs[(40+jj)*33 + b]   + bih1[HSZ+j];
            float xn = Cs[(48+jj)*33 + b]   + bih1[2*HSZ+j];
            float hr = Cs[(64+jj)*33 + b]   + bhh1[j];
            float hz = Cs[(72+jj)*33 + b]   + bhh1[HSZ+j];
            float hn = Cs[(80+jj)*33 + b]   + bhh1[2*HSZ+j];
            float rr = 1.f/(1.f + expf(-(xr + hr)));
            float zz = 1.f/(1.f + expf(-(xz + hz)));
            float nn = tanhf(xn + rr*hn);
            float hp = __ldcg(h1p_32 + (size_t)b*HSZ + j);
            float h = (1.f - zz)*nn + zz*hp;
            g_h1_32[wp*BH + o] = h;
            __nv_bfloat16 hb = __float2bfloat16(h);
            g_h1_bhi[wp*BH + o] = hb;
            g_h1_blo[wp*BH + o] = __float2bfloat16(h - __bfloat162float(hb));
            int step = ph - 1;
            if (step < SSZ) g_enc_out_t[(size_t)step*BH + o] = h;
            else            g_h1_all[(size_t)(step - SSZ)*BH + o] = tf32v(h);
        }
        gbar(&sense);
    }
}

// ---------------- batched attention ----------------
__global__ __launch_bounds__(256) void attn_batched(
    const float* __restrict__ h1_all,
    const float* __restrict__ enc_out_t,
    const int*   __restrict__ src_tokens,
    float* __restrict__ ctx_all)
{
    int b = blockIdx.x, t = blockIdx.y;
    const float* h1t = h1_all + (size_t)t*BH;
    float* ctx = ctx_all + (size_t)t*BH;
    int w = threadIdx.x >> 5, lane = threadIdx.x & 31;
    __shared__ float sc[64];

    float4 q[8];
    #pragma unroll
    for (int c = 0; c < 8; c++)
        q[c] = *(const float4*)(h1t + (size_t)b*HSZ + c*128 + lane*4);

    #pragma unroll
    for (int i = 0; i < 8; i++) {
        int s = w*8 + i;
        const float* e = enc_out_t + ((size_t)s*BSZ + b)*HSZ;
        float acc = 0.f;
        #pragma unroll
        for (int c = 0; c < 8; c++) {
            float4 ev = *(const float4*)(e + c*128 + lane*4);
            acc += q[c].x*ev.x + q[c].y*ev.y + q[c].z*ev.z + q[c].w*ev.w;
        }
        #pragma unroll
        for (int off = 16; off; off >>= 1)
            acc += __shfl_xor_sync(0xffffffffu, acc, off);
        if (lane == 0)
            sc[s] = (src_tokens[s*BSZ + b] != PAD_IDX) ? acc : NEGV;
    }
    __syncthreads();

    if (w == 0) {
        float v0 = sc[lane], v1 = sc[lane+32];
        float m = fmaxf(v0, v1);
        #pragma unroll
        for (int off = 16; off; off >>= 1)
            m = fmaxf(m, __shfl_xor_sync(0xffffffffu, m, off));
        float e0 = expf(v0 - m), e1 = expf(v1 - m);
        float ssum = e0 + e1;
        #pragma unroll
        for (int off = 16; off; off >>= 1)
            ssum += __shfl_xor_sync(0xffffffffu, ssum, off);
        sc[lane]    = e0/ssum;
        sc[lane+32] = e1/ssum;
    }
    __syncthreads();

    float4 a4 = make_float4(0.f, 0.f, 0.f, 0.f);
    for (int s = 0; s < SSZ; s++) {
        float at = sc[s];
        float4 ev = *(const float4*)(enc_out_t + ((size_t)s*BSZ + b)*HSZ + threadIdx.x*4);
        a4.x += at*ev.x; a4.y += at*ev.y; a4.z += at*ev.z; a4.w += at*ev.w;
    }
    uint4 u = make_uint4(f2tf32(a4.x), f2tf32(a4.y), f2tf32(a4.z), f2tf32(a4.w));
    *(uint4*)(ctx + (size_t)b*HSZ + threadIdx.x*4) = u;
}

// ---------------- batched cc GEMM (tf32 mma) ----------------
#define CC_SMEM ((2*128*36 + 2*128*36)*4)
__global__ __launch_bounds__(256) void cc_mma(
    const float* __restrict__ h1a, const float* __restrict__ ctxa,
    const float* __restrict__ wc,  const float* __restrict__ bc,
    float* __restrict__ cc)
{
    extern __shared__ uint32_t sm[];
    uint32_t* As = sm;
    uint32_t* Bs = sm + 2*128*36;

    int tid = threadIdx.x, w = tid >> 5, lane = tid & 31;
    int g = lane >> 2, t4 = lane & 3;
    int warpM = w & 1, warpN = w >> 1;
    int mb = blockIdx.x * 128, nb = blockIdx.y * 128;

    uint32_t as_s = (uint32_t)__cvta_generic_to_shared(As);
    uint32_t bs_s = (uint32_t)__cvta_generic_to_shared(Bs);

    float acc[4][4][4];
    #pragma unroll
    for (int i = 0; i < 4; i++)
        #pragma unroll
        for (int jj = 0; jj < 4; jj++)
            #pragma unroll
            for (int k = 0; k < 4; k++) acc[i][jj][k] = 0.f;

    auto issue = [&](int ch) {
        int kc0 = ch*32, buf = ch & 1;
        uint32_t ao = as_s + buf*128*36*4;
        uint32_t bo2 = bs_s + buf*128*36*4;
        #pragma unroll
        for (int i = 0; i < 4; i++) {
            int idx = tid + i*256, r = idx >> 3, c = (idx & 7)*4;
            int k = kc0 + c;
            const float* src = (k < HSZ) ? (h1a + (size_t)(mb+r)*HSZ + k)
                                         : (ctxa + (size_t)(mb+r)*HSZ + (k - HSZ));
            cp16(ao + (r*36 + c)*4, src);
        }
        #pragma unroll
        for (int i = 0; i < 4; i++) {
            int idx = tid + i*256, r = idx >> 3, c = (idx & 7)*4;
            cp16(bo2 + (r*36 + c)*4, wc + (size_t)(nb+r)*(2*HSZ) + kc0 + c);
        }
        CP_COMMIT();
    };

    issue(0);
    for (int ch = 0; ch < 64; ch++) {
        if (ch < 63) { issue(ch+1); CP_WAIT(1); } else { CP_WAIT(0); }
        __syncthreads();
        int buf = ch & 1;
        const uint32_t* A0 = As + buf*128*36 + (warpM*64 + g)*36;
        const uint32_t* B0 = Bs + buf*128*36 + (warpN*32 + g)*36;
        #pragma unroll
        for (int ks = 0; ks < 4; ks++) {
            uint32_t a[4][4], b[4][2];
            #pragma unroll
            for (int mf = 0; mf < 4; mf++) {
                const uint32_t* ap = A0 + mf*16*36 + ks*8 + t4;
                a[mf][0] = ap[0]; a[mf][1] = ap[8*36]; a[mf][2] = ap[4]; a[mf][3] = ap[8*36+4];
            }
            #pragma unroll
            for (int nf = 0; nf < 4; nf++) {
                const uint32_t* bp = B0 + nf*8*36 + ks*8 + t4;
                b[nf][0] = bp[0]; b[nf][1] = bp[4];
            }
            #pragma unroll
            for (int mf = 0; mf < 4; mf++)
                #pragma unroll
                for (int nf = 0; nf < 4; nf++)
                    mma_tf32(acc[mf][nf], a[mf], b[nf]);
        }
        __syncthreads();
    }

    #pragma unroll
    for (int nf = 0; nf < 4; nf++) {
        int n = nb + warpN*32 + nf*8 + t4*2;
        float b0v = bc[n], b1v = bc[n+1];
        #pragma unroll
        for (int mf = 0; mf < 4; mf++) {
            int m_lo = mb + warpM*64 + mf*16 + g;
            int m_hi = m_lo + 8;
            if (m_lo < (TSZ-1)*BSZ) {
                cc[(size_t)m_lo*HSZ + n  ] = tf32v(tanhf(acc[mf][nf][0] + b0v));
                cc[(size_t)m_lo*HSZ + n+1] = tf32v(tanhf(acc[mf][nf][1] + b1v));
            }
            if (m_hi < (TSZ-1)*BSZ) {
                cc[(size_t)m_hi*HSZ + n  ] = tf32v(tanhf(acc[mf][nf][2] + b0v));
                cc[(size_t)m_hi*HSZ + n+1] = tf32v(tanhf(acc[mf][nf][3] + b1v));
            }
        }
    }
}

// ---------------- logits GEMM (tf32 mma) ----------------
#define LG_SMEM ((2*128*36 + 2*256*36)*4)
__global__ __launch_bounds__(256) void logits_mma(
    const float* __restrict__ cc, const float* __restrict__ wo,
    const float* __restrict__ bo, float* __restrict__ out)
{
    extern __shared__ uint32_t sm[];
    uint32_t* As = sm;
    uint32_t* Bs = sm + 2*128*36;

    int tid = threadIdx.x, w = tid >> 5, lane = tid & 31;
    int g = lane >> 2, t4 = lane & 3;
    int warpM = w & 1, warpN = w >> 1;
    int mb = blockIdx.x * 128, vb = blockIdx.y * 256;

    const float* Ag = cc + (size_t)mb*HSZ;
    const float* Bg = wo + (size_t)vb*HSZ;
    uint32_t as_s = (uint32_t)__cvta_generic_to_shared(As);
    uint32_t bs_s = (uint32_t)__cvta_generic_to_shared(Bs);

    float acc[4][8][4];
    #pragma unroll
    for (int i = 0; i < 4; i++)
        #pragma unroll
        for (int jj = 0; jj < 8; jj++)
            #pragma unroll
            for (int k = 0; k < 4; k++) acc[i][jj][k] = 0.f;

    {
        #pragma unroll
        for (int i = 0; i < 4; i++) {
            int idx = tid + i*256, r = idx >> 3, c = (idx & 7)*4;
            cp16(as_s + (r*36 + c)*4, Ag + (size_t)r*HSZ + c);
        }
        #pragma unroll
        for (int i = 0; i < 8; i++) {
            int idx = tid + i*256, r = idx >> 3, c = (idx & 7)*4;
            cp16(bs_s + (r*36 + c)*4, Bg + (size_t)r*HSZ + c);
        }
        CP_COMMIT();
    }

    for (int ch = 0; ch < 32; ch++) {
        if (ch < 31) {
            int kc0 = (ch+1)*32, buf = (ch+1) & 1;
            uint32_t ao = as_s + buf*128*36*4;
            uint32_t bo_s = bs_s + buf*256*36*4;
            #pragma unroll
            for (int i = 0; i < 4; i++) {
                int idx = tid + i*256, r = idx >> 3, c = (idx & 7)*4;
                cp16(ao + (r*36 + c)*4, Ag + (size_t)r*HSZ + kc0 + c);
            }
            #pragma unroll
            for (int i = 0; i < 8; i++) {
                int idx = tid + i*256, r = idx >> 3, c = (idx & 7)*4;
                cp16(bo_s + (r*36 + c)*4, Bg + (size_t)r*HSZ + kc0 + c);
            }
            CP_COMMIT();
            CP_WAIT(1);
        } else {
            CP_WAIT(0);
        }
        __syncthreads();

        int buf = ch & 1;
        const uint32_t* A0 = As + buf*128*36 + (warpM*64 + g)*36;
        const uint32_t* B0 = Bs + buf*256*36 + (warpN*64 + g)*36;

        #pragma unroll
        for (int ks = 0; ks < 4; ks++) {
            uint32_t a[4][4], b[8][2];
            #pragma unroll
            for (int mf = 0; mf < 4; mf++) {
                const uint32_t* ap = A0 + mf*16*36 + ks*8 + t4;
                a[mf][0] = ap[0]; a[mf][1] = ap[8*36]; a[mf][2] = ap[4]; a[mf][3] = ap[8*36+4];
            }
            #pragma unroll
            for (int nf = 0; nf < 8; nf++) {
                const uint32_t* bp = B0 + nf*8*36 + ks*8 + t4;
                b[nf][0] = bp[0]; b[nf][1] = bp[4];
            }
            #pragma unroll
            for (int mf = 0; mf < 4; mf++)
                #pragma unroll
                for (int nf = 0; nf < 8; nf++)
                    mma_tf32(acc[mf][nf], a[mf], b[nf]);
        }
        __syncthreads();
    }

    #pragma unroll
    for (int nf = 0; nf < 8; nf++) {
        int v = vb + warpN*64 + nf*8 + t4*2;
        float b0v = bo[v], b1v = bo[v+1];
        #pragma unroll
        for (int mf = 0; mf < 4; mf++) {
            int m_lo = mb + warpM*64 + mf*16 + g;
            int m_hi = m_lo + 8;
            if (m_lo < (TSZ-1)*BSZ) {
                out[(size_t)(m_lo + BSZ)*VSZ + v    ] = acc[mf][nf][0] + b0v;
                out[(size_t)(m_lo + BSZ)*VSZ + v + 1] = acc[mf][nf][1] + b1v;
            }
            if (m_hi < (TSZ-1)*BSZ) {
                out[(size_t)(m_hi + BSZ)*VSZ + v    ] = acc[mf][nf][2] + b0v;
                out[(size_t)(m_hi + BSZ)*VSZ + v + 1] = acc[mf][nf][3] + b1v;
            }
        }
    }
}

// ---------------- host ----------------
extern "C" void kernel_launch(void* const* d_in, const int* in_sizes, int n_in,
                              void* d_out, int out_size) {
    const int*   src_tokens = (const int*)  d_in[0];
    const int*   tgt_tokens = (const int*)  d_in[1];
    const float* enc_emb    = (const float*)d_in[2];
    const float* enc_Wih0   = (const float*)d_in[3];
    const float* enc_Whh0   = (const float*)d_in[4];
    const float* enc_bih0   = (const float*)d_in[5];
    const float* enc_bhh0   = (const float*)d_in[6];
    const float* enc_Wih1   = (const float*)d_in[7];
    const float* enc_Whh1   = (const float*)d_in[8];
    const float* enc_bih1   = (const float*)d_in[9];
    const float* enc_bhh1   = (const float*)d_in[10];
    const float* dec_emb    = (const float*)d_in[11];
    const float* dec_Wih0   = (const float*)d_in[12];
    const float* dec_Whh0   = (const float*)d_in[13];
    const float* dec_bih0   = (const float*)d_in[14];
    const float* dec_bhh0   = (const float*)d_in[15];
    const float* dec_Wih1   = (const float*)d_in[16];
    const float* dec_Whh1   = (const float*)d_in[17];
    const float* dec_bih1   = (const float*)d_in[18];
    const float* dec_bhh1   = (const float*)d_in[19];
    const float* Wc         = (const float*)d_in[20];
    const float* bc         = (const float*)d_in[21];
    const float* Wo         = (const float*)d_in[22];
    const float* bo         = (const float*)d_in[23];
    float* out = (float*)d_out;

    float *emb_src, *emb_dec, *gx_enc, *gx_dec, *enc_out_t;
    float *h1_all, *ctx_all, *cc_all, *wo_tf, *wc_tf;
    cudaGetSymbolAddress((void**)&emb_src,   g_emb_src);
    cudaGetSymbolAddress((void**)&emb_dec,   g_emb_dec);
    cudaGetSymbolAddress((void**)&gx_enc,    g_gx_enc);
    cudaGetSymbolAddress((void**)&gx_dec,    g_gx_dec);
    cudaGetSymbolAddress((void**)&enc_out_t, g_enc_out_t);
    cudaGetSymbolAddress((void**)&h1_all,    g_h1_all);
    cudaGetSymbolAddress((void**)&ctx_all,   g_ctx_all);
    cudaGetSymbolAddress((void**)&cc_all,    g_cc_all);
    cudaGetSymbolAddress((void**)&wo_tf,     g_wo_tf);
    cudaGetSymbolAddress((void**)&wc_tf,     g_wc_tf);

    cudaFuncSetAttribute(rnn_persistent, cudaFuncAttributeMaxDynamicSharedMemorySize, RNN_SMEM);
    cudaFuncSetAttribute(proj_mma,      cudaFuncAttributeMaxDynamicSharedMemorySize, PJ_SMEM);
    cudaFuncSetAttribute(cc_mma,        cudaFuncAttributeMaxDynamicSharedMemorySize, CC_SMEM);
    cudaFuncSetAttribute(logits_mma,    cudaFuncAttributeMaxDynamicSharedMemorySize, LG_SMEM);

    // prep (rnn_persistent = launch #6 for ncu)
    embed_kernel<<<(SSZ*BSZ*ESZ)/256, 256>>>(src_tokens, enc_emb, emb_src, SSZ*BSZ);            // 1
    embed_kernel<<<((TSZ-1)*BSZ*ESZ+255)/256, 256>>>(tgt_tokens, dec_emb, emb_dec, (TSZ-1)*BSZ); // 2
    cvt2_wih0<<<(2*(3*HSZ*ESZ/4))/256, 256>>>(enc_Wih0, dec_Wih0);                              // 3
    proj_mma<<<dim3(16, 24, 2), 256, PJ_SMEM>>>(emb_src, emb_dec, enc_bih0, dec_bih0,
                                                gx_enc, gx_dec, SSZ*BSZ, (TSZ-1)*BSZ);          // 4
    split_all<<<(6*(WSZ/4))/256, 256>>>(enc_Whh0, enc_Wih1, enc_Whh1,
                                        dec_Whh0, dec_Wih1, dec_Whh1);                          // 5

    // recurrence: ONE launch, 128 fused phases, bf16 hi/lo                                      // 6
    rnn_persistent<<<NBLK, 256, RNN_SMEM>>>(enc_bhh0, enc_bih1, enc_bhh1,
                                            dec_bhh0, dec_bih1, dec_bhh1);

    // epilogue
    zero_kernel<<<1024, 256>>>(out, BSZ*VSZ);
    cvt_tf32_kernel<<<(VSZ*HSZ/4)/256, 256>>>(Wo, wo_tf);
    cvt_tf32_kernel<<<(HSZ*2*HSZ/4)/256, 256>>>(Wc, wc_tf);
    attn_batched<<<dim3(BSZ, TSZ-1), 256>>>(h1_all, enc_out_t, src_tokens, ctx_all);
    cc_mma<<<dim3(16, 8), 256, CC_SMEM>>>(h1_all, ctx_all, wc_tf, bc, cc_all);
    logits_mma<<<dim3(16, 125), 256, LG_SMEM>>>(cc_all, wo_tf, bo, out);
}